// round 2
// baseline (speedup 1.0000x reference)
#include <cuda_runtime.h>
#include <cuda_bf16.h>
#include <math.h>

// Problem constants
#define BB   2
#define SS   2048
#define HH   4096
#define NHD  32            // query heads
#define NKVH 8             // kv heads
#define DD   128
#define CQKV (NHD*DD + 2*NKVH*DD)   // 6144
#define HALF 64
#define SCALE 0.08838834764831843f  // 1/sqrt(128)

// Scratch (device globals -- allocation-free per harness rules)
__device__ float g_qkv[(size_t)BB*SS*CQKV];        // 4096 x 6144
__device__ float g_q  [(size_t)BB*NHD*SS*DD];      // (b,h,s,d)
__device__ float g_k  [(size_t)BB*NKVH*SS*DD];     // (b,kh,s,d)
__device__ float g_v  [(size_t)BB*NKVH*SS*DD];
__device__ float g_o  [(size_t)BB*SS*NHD*DD];      // (b,s, h*D) rows for final GEMM
__device__ float g_cos[SS*HALF];
__device__ float g_sin[SS*HALF];

// ---------------------------------------------------------------------------
// RoPE cos/sin tables (double precision pow to keep angle error << 1e-4)
// ---------------------------------------------------------------------------
__global__ void build_tables_kernel(const int* __restrict__ positions) {
    int idx = blockIdx.x * blockDim.x + threadIdx.x;
    if (idx >= SS * HALF) return;
    int s = idx >> 6;
    int i = idx & 63;
    double inv = pow(10000.0, -((double)(2 * i)) / (double)DD);
    double ang = (double)positions[s] * inv;
    g_cos[idx] = (float)cos(ang);
    g_sin[idx] = (float)sin(ang);
}

// ---------------------------------------------------------------------------
// SGEMM: C[M,N] = A[M,K] @ B[K,N], row-major. 128x128x16 tiles, 8x8/thread.
// M,N,K multiples of 128/16 here (4096, 4096/6144, 4096).
// ---------------------------------------------------------------------------
__global__ __launch_bounds__(256, 2)
void sgemm_kernel(int M, int N, int K,
                  const float* __restrict__ A,
                  const float* __restrict__ B,
                  float* __restrict__ C) {
    __shared__ float As[16][128];   // [k][m] (transposed on load)
    __shared__ float Bs[16][128];   // [k][n]

    const int tid  = threadIdx.x;
    const size_t brow = blockIdx.y;
    const size_t bcol = blockIdx.x;
    const float* Ab = A + brow * 128 * (size_t)K;
    const float* Bb = B + bcol * 128;

    float acc[8][8];
#pragma unroll
    for (int i = 0; i < 8; i++)
#pragma unroll
        for (int j = 0; j < 8; j++) acc[i][j] = 0.f;

    const int ty = tid >> 4;   // 0..15
    const int tx = tid & 15;   // 0..15

    for (int k0 = 0; k0 < K; k0 += 16) {
        // Load A tile 128x16 (transposed into As)
#pragma unroll
        for (int t = 0; t < 2; t++) {
            int id = tid + t * 256;           // 0..511
            int r  = id >> 2;                 // 0..127
            int c4 = (id & 3) * 4;            // 0,4,8,12
            float4 v = *(const float4*)(Ab + (size_t)r * K + k0 + c4);
            As[c4 + 0][r] = v.x;
            As[c4 + 1][r] = v.y;
            As[c4 + 2][r] = v.z;
            As[c4 + 3][r] = v.w;
        }
        // Load B tile 16x128
#pragma unroll
        for (int t = 0; t < 2; t++) {
            int id = tid + t * 256;           // 0..511
            int r  = id >> 5;                 // 0..15
            int c4 = (id & 31) * 4;           // 0..124
            float4 v = *(const float4*)(Bb + (size_t)(k0 + r) * N + c4);
            *(float4*)&Bs[r][c4] = v;
        }
        __syncthreads();

#pragma unroll
        for (int kk = 0; kk < 16; kk++) {
            float a[8], b[8];
            *(float4*)&a[0] = *(const float4*)&As[kk][ty * 8];
            *(float4*)&a[4] = *(const float4*)&As[kk][ty * 8 + 4];
            *(float4*)&b[0] = *(const float4*)&Bs[kk][tx * 8];
            *(float4*)&b[4] = *(const float4*)&Bs[kk][tx * 8 + 4];
#pragma unroll
            for (int i = 0; i < 8; i++)
#pragma unroll
                for (int j = 0; j < 8; j++)
                    acc[i][j] = fmaf(a[i], b[j], acc[i][j]);
        }
        __syncthreads();
    }

#pragma unroll
    for (int i = 0; i < 8; i++) {
        float* Crow = C + (brow * 128 + ty * 8 + i) * (size_t)N + bcol * 128 + tx * 8;
        *(float4*)(Crow)     = make_float4(acc[i][0], acc[i][1], acc[i][2], acc[i][3]);
        *(float4*)(Crow + 4) = make_float4(acc[i][4], acc[i][5], acc[i][6], acc[i][7]);
    }
}

// ---------------------------------------------------------------------------
// RoPE + scatter: qkv rows (b*S+s, 6144) -> Q(b,h,s,d)*scale, K(b,kh,s,d), V
// ---------------------------------------------------------------------------
__global__ void rope_scatter_kernel() {
    const int m = blockIdx.x;          // b*S + s
    const int b = m / SS;
    const int s = m % SS;
    const float* row = g_qkv + (size_t)m * CQKV;
    const float* ct = g_cos + s * HALF;
    const float* st = g_sin + s * HALF;

    // Q: NH heads x 64 pairs
    for (int idx = threadIdx.x; idx < NHD * HALF; idx += blockDim.x) {
        int h = idx >> 6, i = idx & 63;
        float x1 = row[h * DD + i];
        float x2 = row[h * DD + i + HALF];
        float c = ct[i], sn = st[i];
        float* dst = g_q + (((size_t)(b * NHD + h)) * SS + s) * DD;
        dst[i]        = (x1 * c - x2 * sn) * SCALE;
        dst[i + HALF] = (x2 * c + x1 * sn) * SCALE;
    }
    // K: NKV heads x 64 pairs
    for (int idx = threadIdx.x; idx < NKVH * HALF; idx += blockDim.x) {
        int h = idx >> 6, i = idx & 63;
        float x1 = row[NHD * DD + h * DD + i];
        float x2 = row[NHD * DD + h * DD + i + HALF];
        float c = ct[i], sn = st[i];
        float* dst = g_k + (((size_t)(b * NKVH + h)) * SS + s) * DD;
        dst[i]        = x1 * c - x2 * sn;
        dst[i + HALF] = x2 * c + x1 * sn;
    }
    // V: plain copy
    for (int idx = threadIdx.x; idx < NKVH * DD; idx += blockDim.x) {
        int h = idx >> 7, d = idx & 127;
        g_v[(((size_t)(b * NKVH + h)) * SS + s) * DD + d] =
            row[NHD * DD + NKVH * DD + h * DD + d];
    }
}

// ---------------------------------------------------------------------------
// Flash attention (causal, GQA rep=4). Block = (qtile of 64 rows, head, batch).
// 256 threads: 4 threads/row, each owns a 32-dim slice of D.
// K-tile = 32 rows staged in smem.
// ---------------------------------------------------------------------------
__global__ __launch_bounds__(256, 1)
void flash_kernel() {
    __shared__ float4 Ks[32 * 32];   // [j][c4]
    __shared__ float4 Vs[32 * 32];

    const int qt = blockIdx.x;       // 0..31
    const int h  = blockIdx.y;       // 0..31
    const int b  = blockIdx.z;       // 0..1
    const int tid  = threadIdx.x;
    const int row  = tid >> 2;       // 0..63
    const int part = tid & 3;        // 0..3
    const int qglob = qt * 64 + row;

    const float* qrow = g_q + (((size_t)(b * NHD + h)) * SS + qglob) * DD + part * 32;
    float4 q4[8];
#pragma unroll
    for (int i = 0; i < 8; i++) q4[i] = *(const float4*)(qrow + i * 4);

    const int kh = h >> 2;
    const float* Kbase = g_k + ((size_t)(b * NKVH + kh)) * SS * DD;
    const float* Vbase = g_v + ((size_t)(b * NKVH + kh)) * SS * DD;

    float4 acc[8];
#pragma unroll
    for (int i = 0; i < 8; i++) acc[i] = make_float4(0.f, 0.f, 0.f, 0.f);
    float m = -1e30f, l = 0.f;

    const int ntiles = qt * 2 + 2;   // k tiles up to and incl. diagonal
    for (int t = 0; t < ntiles; t++) {
        const int kstart = t * 32;
        __syncthreads();
#pragma unroll
        for (int u = 0; u < 4; u++) {
            int id = tid + u * 256;           // 0..1023
            int j  = id >> 5;
            int c4 = id & 31;
            Ks[id] = *(const float4*)(Kbase + (size_t)(kstart + j) * DD + c4 * 4);
            Vs[id] = *(const float4*)(Vbase + (size_t)(kstart + j) * DD + c4 * 4);
        }
        __syncthreads();

        float sv[32];
#pragma unroll
        for (int j = 0; j < 32; j++) {
            float p = 0.f;
#pragma unroll
            for (int i = 0; i < 8; i++) {
                float4 kk = Ks[j * 32 + part * 8 + i];
                p = fmaf(q4[i].x, kk.x, p);
                p = fmaf(q4[i].y, kk.y, p);
                p = fmaf(q4[i].z, kk.z, p);
                p = fmaf(q4[i].w, kk.w, p);
            }
            p += __shfl_xor_sync(0xffffffffu, p, 1);
            p += __shfl_xor_sync(0xffffffffu, p, 2);
            sv[j] = (kstart + j <= qglob) ? p : -1e30f;
        }

        float tm = -1e30f;
#pragma unroll
        for (int j = 0; j < 32; j++) tm = fmaxf(tm, sv[j]);
        float mn = fmaxf(m, tm);
        float alpha = __expf(m - mn);
        l *= alpha;
#pragma unroll
        for (int i = 0; i < 8; i++) {
            acc[i].x *= alpha; acc[i].y *= alpha;
            acc[i].z *= alpha; acc[i].w *= alpha;
        }
#pragma unroll
        for (int j = 0; j < 32; j++) {
            float pj = (sv[j] > -1e29f) ? __expf(sv[j] - mn) : 0.f;
            l += pj;
#pragma unroll
            for (int i = 0; i < 8; i++) {
                float4 vv = Vs[j * 32 + part * 8 + i];
                acc[i].x = fmaf(pj, vv.x, acc[i].x);
                acc[i].y = fmaf(pj, vv.y, acc[i].y);
                acc[i].z = fmaf(pj, vv.z, acc[i].z);
                acc[i].w = fmaf(pj, vv.w, acc[i].w);
            }
        }
        m = mn;
    }

    const float inv = 1.f / l;
    float* orow = g_o + ((size_t)(b * SS + qglob)) * (NHD * DD) + h * DD + part * 32;
#pragma unroll
    for (int i = 0; i < 8; i++) {
        float4 o = acc[i];
        o.x *= inv; o.y *= inv; o.z *= inv; o.w *= inv;
        *(float4*)(orow + i * 4) = o;
    }
}

// ---------------------------------------------------------------------------
// Launch
// ---------------------------------------------------------------------------
extern "C" void kernel_launch(void* const* d_in, const int* in_sizes, int n_in,
                              void* d_out, int out_size) {
    const int*   positions = (const int*)d_in[0];
    const float* hidden    = (const float*)d_in[1];
    const float* w_qkv     = (const float*)d_in[2];
    const float* w_o       = (const float*)d_in[3];
    float*       out       = (float*)d_out;

    float *qkv, *oacc;
    cudaGetSymbolAddress((void**)&qkv,  g_qkv);
    cudaGetSymbolAddress((void**)&oacc, g_o);

    // 1) RoPE tables
    build_tables_kernel<<<(SS * HALF + 255) / 256, 256>>>(positions);

    // 2) QKV GEMM: (B*S, H) @ (H, 6144)
    {
        dim3 grid(CQKV / 128, (BB * SS) / 128);
        sgemm_kernel<<<grid, 256>>>(BB * SS, CQKV, HH, hidden, w_qkv, qkv);
    }

    // 3) RoPE + scatter to (b,h,s,d) layouts
    rope_scatter_kernel<<<BB * SS, 256>>>();

    // 4) Flash attention
    {
        dim3 grid(SS / 64, NHD, BB);
        flash_kernel<<<grid, 256>>>();
    }

    // 5) Output projection: (B*S, 4096) @ (4096, 4096)
    {
        dim3 grid(HH / 128, (BB * SS) / 128);
        sgemm_kernel<<<grid, 256>>>(BB * SS, HH, NHD * DD, oacc, w_o, out);
    }
}

// round 3
// speedup vs baseline: 3.0897x; 3.0897x over previous
#include <cuda_runtime.h>
#include <math.h>

#define BB   2
#define SS   2048
#define HH   4096
#define NHD  32
#define NKVH 8
#define DD   128
#define CQKV 6144
#define HALF 64
#define SCALE 0.08838834764831843f

// Scratch (device globals -- allocation-free per harness rules)
__device__ float g_qkv[(size_t)BB*SS*CQKV];
__device__ float g_q  [(size_t)BB*NHD*SS*DD];
__device__ float g_k  [(size_t)BB*NKVH*SS*DD];
__device__ float g_v  [(size_t)BB*NKVH*SS*DD];
__device__ float g_o  [(size_t)BB*SS*NHD*DD];
__device__ float g_cos[SS*HALF];
__device__ float g_sin[SS*HALF];

// ---------------------------------------------------------------------------
// helpers: tf32 convert + m16n8k8 tf32 mma
// ---------------------------------------------------------------------------
__device__ __forceinline__ unsigned f2tf(float x) {
    unsigned r;
    asm("cvt.rna.tf32.f32 %0, %1;" : "=r"(r) : "f"(x));
    return r;
}

__device__ __forceinline__ void mma8(float* c, const unsigned* a, const unsigned* b) {
    asm volatile(
        "mma.sync.aligned.m16n8k8.row.col.f32.tf32.tf32.f32 "
        "{%0,%1,%2,%3}, {%4,%5,%6,%7}, {%8,%9}, {%0,%1,%2,%3};"
        : "+f"(c[0]), "+f"(c[1]), "+f"(c[2]), "+f"(c[3])
        : "r"(a[0]), "r"(a[1]), "r"(a[2]), "r"(a[3]), "r"(b[0]), "r"(b[1]));
}

// ---------------------------------------------------------------------------
// RoPE tables
// ---------------------------------------------------------------------------
__global__ void build_tables_kernel(const int* __restrict__ positions) {
    int idx = blockIdx.x * blockDim.x + threadIdx.x;
    if (idx >= SS * HALF) return;
    int s = idx >> 6;
    int i = idx & 63;
    double inv = pow(10000.0, -((double)(2 * i)) / (double)DD);
    double ang = (double)positions[s] * inv;
    g_cos[idx] = (float)cos(ang);
    g_sin[idx] = (float)sin(ang);
}

// ---------------------------------------------------------------------------
// tf32 tensor-core GEMM: C[M,N] = A[M,K] @ B[K,N], row-major.
// 128x128x16 tiles, 256 threads (8 warps as 4x2, warp tile 32x64).
// SPLIT=true: A,B decomposed hi+lo (3 mma passes) for ~fp32 accuracy.
// ---------------------------------------------------------------------------
#define GP 136   // smem pitch in floats (136 mod 32 == 8 -> conflict-free frags)

template<bool SPLIT>
__global__ __launch_bounds__(256, 1)
void tgemm_kernel(int M, int N, int K,
                  const float* __restrict__ A,
                  const float* __restrict__ B,
                  float* __restrict__ C) {
    __shared__ unsigned Ah[16 * GP];
    __shared__ unsigned Bh[16 * GP];
    __shared__ unsigned Al[SPLIT ? 16 * GP : 1];
    __shared__ unsigned Bl[SPLIT ? 16 * GP : 1];

    const int tid  = threadIdx.x;
    const int wid  = tid >> 5;
    const int lane = tid & 31;
    const int wm = wid >> 1;          // 0..3 (rows of 32)
    const int wn = wid & 1;           // 0..1 (cols of 64)
    const int group = lane >> 2;      // 0..7
    const int tg    = lane & 3;       // 0..3
    const size_t brow = blockIdx.y;
    const size_t bcol = blockIdx.x;

    const float* Abase = A + brow * 128 * (size_t)K;
    const float* Bbase = B + bcol * 128;

    // gmem load assignments (2 float4 each for A and B tile)
    const int ar0 = tid >> 2,          ac0 = (tid & 3) * 4;
    const int ar1 = (tid + 256) >> 2,  ac1 = ((tid + 256) & 3) * 4;
    const int br0 = tid >> 5,          bc0 = (tid & 31) * 4;
    const int br1 = (tid + 256) >> 5,  bc1 = ((tid + 256) & 31) * 4;

    float acc[2][8][4];
#pragma unroll
    for (int mt = 0; mt < 2; mt++)
#pragma unroll
        for (int nt = 0; nt < 8; nt++)
#pragma unroll
            for (int i = 0; i < 4; i++) acc[mt][nt][i] = 0.f;

    float4 pa0 = *(const float4*)(Abase + (size_t)ar0 * K + ac0);
    float4 pa1 = *(const float4*)(Abase + (size_t)ar1 * K + ac1);
    float4 pb0 = *(const float4*)(Bbase + (size_t)br0 * N + bc0);
    float4 pb1 = *(const float4*)(Bbase + (size_t)br1 * N + bc1);

    for (int k0 = 0; k0 < K; k0 += 16) {
        // store staged regs -> smem (split hi/lo)
        {
            float xs[8] = {pa0.x, pa0.y, pa0.z, pa0.w, pa1.x, pa1.y, pa1.z, pa1.w};
            float ys[8] = {pb0.x, pb0.y, pb0.z, pb0.w, pb1.x, pb1.y, pb1.z, pb1.w};
#pragma unroll
            for (int j = 0; j < 4; j++) {
                unsigned h0 = f2tf(xs[j]);
                Ah[(ac0 + j) * GP + ar0] = h0;
                if (SPLIT) Al[(ac0 + j) * GP + ar0] = f2tf(xs[j] - __uint_as_float(h0));
                unsigned h1 = f2tf(xs[4 + j]);
                Ah[(ac1 + j) * GP + ar1] = h1;
                if (SPLIT) Al[(ac1 + j) * GP + ar1] = f2tf(xs[4 + j] - __uint_as_float(h1));
                unsigned g0 = f2tf(ys[j]);
                Bh[br0 * GP + bc0 + j] = g0;
                if (SPLIT) Bl[br0 * GP + bc0 + j] = f2tf(ys[j] - __uint_as_float(g0));
                unsigned g1 = f2tf(ys[4 + j]);
                Bh[br1 * GP + bc1 + j] = g1;
                if (SPLIT) Bl[br1 * GP + bc1 + j] = f2tf(ys[4 + j] - __uint_as_float(g1));
            }
        }
        __syncthreads();

        if (k0 + 16 < K) {
            pa0 = *(const float4*)(Abase + (size_t)ar0 * K + k0 + 16 + ac0);
            pa1 = *(const float4*)(Abase + (size_t)ar1 * K + k0 + 16 + ac1);
            pb0 = *(const float4*)(Bbase + (size_t)(k0 + 16 + br0) * N + bc0);
            pb1 = *(const float4*)(Bbase + (size_t)(k0 + 16 + br1) * N + bc1);
        }

#pragma unroll
        for (int ks = 0; ks < 2; ks++) {
            const int kk = ks * 8 + tg;
            unsigned ah[2][4], al[2][4], bh[8][2], bl[8][2];
#pragma unroll
            for (int mt = 0; mt < 2; mt++) {
                int m = wm * 32 + mt * 16 + group;
                ah[mt][0] = Ah[kk * GP + m];
                ah[mt][1] = Ah[kk * GP + m + 8];
                ah[mt][2] = Ah[(kk + 4) * GP + m];
                ah[mt][3] = Ah[(kk + 4) * GP + m + 8];
                if (SPLIT) {
                    al[mt][0] = Al[kk * GP + m];
                    al[mt][1] = Al[kk * GP + m + 8];
                    al[mt][2] = Al[(kk + 4) * GP + m];
                    al[mt][3] = Al[(kk + 4) * GP + m + 8];
                }
            }
#pragma unroll
            for (int nt = 0; nt < 8; nt++) {
                int n = wn * 64 + nt * 8 + group;
                bh[nt][0] = Bh[kk * GP + n];
                bh[nt][1] = Bh[(kk + 4) * GP + n];
                if (SPLIT) {
                    bl[nt][0] = Bl[kk * GP + n];
                    bl[nt][1] = Bl[(kk + 4) * GP + n];
                }
            }
#pragma unroll
            for (int mt = 0; mt < 2; mt++)
#pragma unroll
                for (int nt = 0; nt < 8; nt++) {
                    mma8(acc[mt][nt], ah[mt], bh[nt]);
                    if (SPLIT) {
                        mma8(acc[mt][nt], ah[mt], bl[nt]);
                        mma8(acc[mt][nt], al[mt], bh[nt]);
                    }
                }
        }
        __syncthreads();
    }

    // epilogue
#pragma unroll
    for (int mt = 0; mt < 2; mt++)
#pragma unroll
        for (int nt = 0; nt < 8; nt++) {
            size_t row = brow * 128 + wm * 32 + mt * 16 + group;
            size_t col = bcol * 128 + wn * 64 + nt * 8 + 2 * tg;
            *(float2*)(C + row * N + col) =
                make_float2(acc[mt][nt][0], acc[mt][nt][1]);
            *(float2*)(C + (row + 8) * N + col) =
                make_float2(acc[mt][nt][2], acc[mt][nt][3]);
        }
}

// ---------------------------------------------------------------------------
// RoPE + scatter
// ---------------------------------------------------------------------------
__global__ void rope_scatter_kernel() {
    const int m = blockIdx.x;
    const int b = m / SS;
    const int s = m % SS;
    const float* row = g_qkv + (size_t)m * CQKV;
    const float* ct = g_cos + s * HALF;
    const float* st = g_sin + s * HALF;

    for (int idx = threadIdx.x; idx < NHD * HALF; idx += blockDim.x) {
        int h = idx >> 6, i = idx & 63;
        float x1 = row[h * DD + i];
        float x2 = row[h * DD + i + HALF];
        float c = ct[i], sn = st[i];
        float* dst = g_q + (((size_t)(b * NHD + h)) * SS + s) * DD;
        dst[i]        = (x1 * c - x2 * sn) * SCALE;
        dst[i + HALF] = (x2 * c + x1 * sn) * SCALE;
    }
    for (int idx = threadIdx.x; idx < NKVH * HALF; idx += blockDim.x) {
        int h = idx >> 6, i = idx & 63;
        float x1 = row[NHD * DD + h * DD + i];
        float x2 = row[NHD * DD + h * DD + i + HALF];
        float c = ct[i], sn = st[i];
        float* dst = g_k + (((size_t)(b * NKVH + h)) * SS + s) * DD;
        dst[i]        = x1 * c - x2 * sn;
        dst[i + HALF] = x2 * c + x1 * sn;
    }
    for (int idx = threadIdx.x; idx < NKVH * DD; idx += blockDim.x) {
        int h = idx >> 7, d = idx & 127;
        g_v[(((size_t)(b * NKVH + h)) * SS + s) * DD + d] =
            row[NHD * DD + NKVH * DD + h * DD + d];
    }
}

// ---------------------------------------------------------------------------
// Flash attention with tf32 mma. Block = 64 q rows, 4 warps (16 rows each).
// Key tile = 64. Scores: split-tf32 (3 mma). PV: single tf32.
// ---------------------------------------------------------------------------
#define FQP 132   // Q/K pitch (132 mod 32 == 4: group-indexed rows conflict-free)
#define FVP 136   // V pitch   (136 mod 32 == 8: tg-indexed rows conflict-free)
#define FPP 68    // P pitch
#define FLASH_SMEM ((4 * 64 * FQP + 64 * FVP + 64 * FPP) * 4)

__global__ __launch_bounds__(128, 1)
void flash2_kernel() {
    extern __shared__ unsigned sm[];
    unsigned* Qh = sm;
    unsigned* Ql = Qh + 64 * FQP;
    unsigned* Kh = Ql + 64 * FQP;
    unsigned* Kl = Kh + 64 * FQP;
    unsigned* Vs = Kl + 64 * FQP;
    unsigned* Ps = Vs + 64 * FVP;

    const int bx = blockIdx.x, h = blockIdx.y, b = blockIdx.z;
    const int tid = threadIdx.x, wid = tid >> 5, lane = tid & 31;
    const int group = lane >> 2, tg = lane & 3;
    const int qbase = bx * 64;
    const int kh = h >> 2;

    const float* Qg = g_q + (((size_t)(b * NHD + h)) * SS + qbase) * DD;
    const float* Kg = g_k + ((size_t)(b * NKVH + kh)) * SS * DD;
    const float* Vg = g_v + ((size_t)(b * NKVH + kh)) * SS * DD;

    // stage Q (hi+lo)
#pragma unroll
    for (int i = 0; i < 16; i++) {
        int id = tid + i * 128;
        int r = id >> 5, c4 = (id & 31) * 4;
        float4 v = *(const float4*)(Qg + (size_t)r * DD + c4);
        float xs[4] = {v.x, v.y, v.z, v.w};
#pragma unroll
        for (int j = 0; j < 4; j++) {
            unsigned hh = f2tf(xs[j]);
            Qh[r * FQP + c4 + j] = hh;
            Ql[r * FQP + c4 + j] = f2tf(xs[j] - __uint_as_float(hh));
        }
    }

    float Oa[16][4];
#pragma unroll
    for (int dt = 0; dt < 16; dt++)
#pragma unroll
        for (int i = 0; i < 4; i++) Oa[dt][i] = 0.f;
    float m0 = -1e30f, m1 = -1e30f, l0 = 0.f, l1 = 0.f;

    const int ntile = bx + 1;
    for (int t = 0; t < ntile; t++) {
        __syncthreads();
        const float* Kt = Kg + (size_t)t * 64 * DD;
        const float* Vt = Vg + (size_t)t * 64 * DD;
#pragma unroll
        for (int i = 0; i < 16; i++) {
            int id = tid + i * 128;
            int r = id >> 5, c4 = (id & 31) * 4;
            float4 v = *(const float4*)(Kt + (size_t)r * DD + c4);
            float4 w = *(const float4*)(Vt + (size_t)r * DD + c4);
            float xs[4] = {v.x, v.y, v.z, v.w};
            float ys[4] = {w.x, w.y, w.z, w.w};
#pragma unroll
            for (int j = 0; j < 4; j++) {
                unsigned hh = f2tf(xs[j]);
                Kh[r * FQP + c4 + j] = hh;
                Kl[r * FQP + c4 + j] = f2tf(xs[j] - __uint_as_float(hh));
                Vs[r * FVP + c4 + j] = f2tf(ys[j]);
            }
        }
        __syncthreads();

        // scores: S(16x64 per warp) = Q(16x128) @ K^T, split-tf32
        float sacc[8][4];
#pragma unroll
        for (int nt = 0; nt < 8; nt++)
#pragma unroll
            for (int i = 0; i < 4; i++) sacc[nt][i] = 0.f;

        const int qr = wid * 16 + group;
#pragma unroll
        for (int ks = 0; ks < 16; ks++) {
            const int kk = ks * 8 + tg;
            unsigned ah[4], al[4];
            ah[0] = Qh[qr * FQP + kk];       ah[1] = Qh[(qr + 8) * FQP + kk];
            ah[2] = Qh[qr * FQP + kk + 4];   ah[3] = Qh[(qr + 8) * FQP + kk + 4];
            al[0] = Ql[qr * FQP + kk];       al[1] = Ql[(qr + 8) * FQP + kk];
            al[2] = Ql[qr * FQP + kk + 4];   al[3] = Ql[(qr + 8) * FQP + kk + 4];
#pragma unroll
            for (int nt = 0; nt < 8; nt++) {
                int key = nt * 8 + group;
                unsigned bh[2], bl[2];
                bh[0] = Kh[key * FQP + kk];
                bh[1] = Kh[key * FQP + kk + 4];
                bl[0] = Kl[key * FQP + kk];
                bl[1] = Kl[key * FQP + kk + 4];
                mma8(sacc[nt], ah, bh);
                mma8(sacc[nt], ah, bl);
                mma8(sacc[nt], al, bh);
            }
        }

        // causal mask on diagonal tile
        if (t == bx) {
            int r0 = qbase + wid * 16 + group, r1 = r0 + 8;
#pragma unroll
            for (int nt = 0; nt < 8; nt++) {
                int c0 = t * 64 + nt * 8 + 2 * tg, c1 = c0 + 1;
                if (c0 > r0) sacc[nt][0] = -1e30f;
                if (c1 > r0) sacc[nt][1] = -1e30f;
                if (c0 > r1) sacc[nt][2] = -1e30f;
                if (c1 > r1) sacc[nt][3] = -1e30f;
            }
        }

        // online softmax
        float tm0 = -1e30f, tm1 = -1e30f;
#pragma unroll
        for (int nt = 0; nt < 8; nt++) {
            tm0 = fmaxf(tm0, fmaxf(sacc[nt][0], sacc[nt][1]));
            tm1 = fmaxf(tm1, fmaxf(sacc[nt][2], sacc[nt][3]));
        }
        tm0 = fmaxf(tm0, __shfl_xor_sync(0xffffffffu, tm0, 1));
        tm0 = fmaxf(tm0, __shfl_xor_sync(0xffffffffu, tm0, 2));
        tm1 = fmaxf(tm1, __shfl_xor_sync(0xffffffffu, tm1, 1));
        tm1 = fmaxf(tm1, __shfl_xor_sync(0xffffffffu, tm1, 2));

        float mn0 = fmaxf(m0, tm0), mn1 = fmaxf(m1, tm1);
        float a0 = __expf(m0 - mn0), a1 = __expf(m1 - mn1);
        l0 *= a0; l1 *= a1;
#pragma unroll
        for (int dt = 0; dt < 16; dt++) {
            Oa[dt][0] *= a0; Oa[dt][1] *= a0;
            Oa[dt][2] *= a1; Oa[dt][3] *= a1;
        }

        float rs0 = 0.f, rs1 = 0.f;
        const int pr = wid * 16 + group;
#pragma unroll
        for (int nt = 0; nt < 8; nt++) {
            float p0 = __expf(sacc[nt][0] - mn0);
            float p1 = __expf(sacc[nt][1] - mn0);
            float p2 = __expf(sacc[nt][2] - mn1);
            float p3 = __expf(sacc[nt][3] - mn1);
            unsigned u0 = f2tf(p0), u1 = f2tf(p1), u2 = f2tf(p2), u3 = f2tf(p3);
            rs0 += __uint_as_float(u0) + __uint_as_float(u1);
            rs1 += __uint_as_float(u2) + __uint_as_float(u3);
            int c = nt * 8 + 2 * tg;
            Ps[pr * FPP + c] = u0;       Ps[pr * FPP + c + 1] = u1;
            Ps[(pr + 8) * FPP + c] = u2; Ps[(pr + 8) * FPP + c + 1] = u3;
        }
        rs0 += __shfl_xor_sync(0xffffffffu, rs0, 1);
        rs0 += __shfl_xor_sync(0xffffffffu, rs0, 2);
        rs1 += __shfl_xor_sync(0xffffffffu, rs1, 1);
        rs1 += __shfl_xor_sync(0xffffffffu, rs1, 2);
        l0 += rs0; l1 += rs1;
        m0 = mn0; m1 = mn1;

        __syncwarp();

        // O(16x128 per warp) += P(16x64) @ V(64x128), single tf32
#pragma unroll
        for (int ks = 0; ks < 8; ks++) {
            const int kk = ks * 8 + tg;
            unsigned a[4];
            a[0] = Ps[pr * FPP + kk];       a[1] = Ps[(pr + 8) * FPP + kk];
            a[2] = Ps[pr * FPP + kk + 4];   a[3] = Ps[(pr + 8) * FPP + kk + 4];
#pragma unroll
            for (int dt = 0; dt < 16; dt++) {
                unsigned bv[2];
                bv[0] = Vs[kk * FVP + dt * 8 + group];
                bv[1] = Vs[(kk + 4) * FVP + dt * 8 + group];
                mma8(Oa[dt], a, bv);
            }
        }
    }

    // epilogue
    float inv0 = 1.f / l0, inv1 = 1.f / l1;
    int r0 = qbase + wid * 16 + group;
    float* O0 = g_o + ((size_t)(b * SS) + r0) * (NHD * DD) + h * DD;
    float* O1 = g_o + ((size_t)(b * SS) + r0 + 8) * (NHD * DD) + h * DD;
#pragma unroll
    for (int dt = 0; dt < 16; dt++) {
        int c = dt * 8 + 2 * tg;
        *(float2*)(O0 + c) = make_float2(Oa[dt][0] * inv0, Oa[dt][1] * inv0);
        *(float2*)(O1 + c) = make_float2(Oa[dt][2] * inv1, Oa[dt][3] * inv1);
    }
}

// ---------------------------------------------------------------------------
// Launch
// ---------------------------------------------------------------------------
extern "C" void kernel_launch(void* const* d_in, const int* in_sizes, int n_in,
                              void* d_out, int out_size) {
    const int*   positions = (const int*)d_in[0];
    const float* hidden    = (const float*)d_in[1];
    const float* w_qkv     = (const float*)d_in[2];
    const float* w_o       = (const float*)d_in[3];
    float*       out       = (float*)d_out;

    float *qkv, *oacc;
    cudaGetSymbolAddress((void**)&qkv,  g_qkv);
    cudaGetSymbolAddress((void**)&oacc, g_o);

    cudaFuncSetAttribute(flash2_kernel,
                         cudaFuncAttributeMaxDynamicSharedMemorySize, FLASH_SMEM);

    // 1) RoPE tables
    build_tables_kernel<<<(SS * HALF + 255) / 256, 256>>>(positions);

    // 2) QKV GEMM (split-tf32): (B*S, H) @ (H, 6144)
    {
        dim3 grid(CQKV / 128, (BB * SS) / 128);
        tgemm_kernel<true><<<grid, 256>>>(BB * SS, CQKV, HH, hidden, w_qkv, qkv);
    }

    // 3) RoPE + scatter
    rope_scatter_kernel<<<BB * SS, 256>>>();

    // 4) Flash attention (tf32 mma)
    {
        dim3 grid(SS / 64, NHD, BB);
        flash2_kernel<<<grid, 128, FLASH_SMEM>>>();
    }

    // 5) Output projection (single tf32): (B*S, 4096) @ (4096, 4096)
    {
        dim3 grid(HH / 128, (BB * SS) / 128);
        tgemm_kernel<false><<<grid, 256>>>(BB * SS, HH, NHD * DD, oacc, w_o, out);
    }
}

// round 4
// speedup vs baseline: 4.6073x; 1.4912x over previous
#include <cuda_runtime.h>
#include <cuda_bf16.h>
#include <math.h>

#define BB   2
#define SS   2048
#define HH   4096
#define NHD  32
#define NKVH 8
#define DD   128
#define CQKV 6144
#define MM   (BB*SS)         // 4096
#define HALF 64
#define SCALE 0.08838834764831843f

typedef __nv_bfloat16 bf16;

// ---------------- device scratch (allocation-free) ----------------
__device__ float g_qkv [(size_t)MM*CQKV];
__device__ bf16  g_hidh[(size_t)MM*HH],    g_hidl[(size_t)MM*HH];
__device__ bf16  g_wqTh[(size_t)CQKV*HH],  g_wqTl[(size_t)CQKV*HH];
__device__ bf16  g_woTh[(size_t)HH*HH],    g_woTl[(size_t)HH*HH];
__device__ bf16  g_qh[(size_t)BB*NHD*SS*DD],  g_ql[(size_t)BB*NHD*SS*DD];
__device__ bf16  g_kh[(size_t)BB*NKVH*SS*DD], g_kl[(size_t)BB*NKVH*SS*DD];
__device__ bf16  g_vth[(size_t)BB*NKVH*DD*SS], g_vtl[(size_t)BB*NKVH*DD*SS];
__device__ bf16  g_oh[(size_t)MM*HH],      g_ol[(size_t)MM*HH];
__device__ float g_cos[SS*HALF], g_sin[SS*HALF];

// ---------------- helpers ----------------
__device__ __forceinline__ void cpa16(unsigned d, const void* s) {
    asm volatile("cp.async.ca.shared.global [%0], [%1], 16;" :: "r"(d), "l"(s));
}
__device__ __forceinline__ void cpa_commit() {
    asm volatile("cp.async.commit_group;");
}
template<int N>
__device__ __forceinline__ void cpa_wait() {
    asm volatile("cp.async.wait_group %0;" :: "n"(N));
}
__device__ __forceinline__ void mma16(float* c, const unsigned* a, const unsigned* b) {
    asm volatile(
        "mma.sync.aligned.m16n8k16.row.col.f32.bf16.bf16.f32 "
        "{%0,%1,%2,%3}, {%4,%5,%6,%7}, {%8,%9}, {%0,%1,%2,%3};"
        : "+f"(c[0]), "+f"(c[1]), "+f"(c[2]), "+f"(c[3])
        : "r"(a[0]), "r"(a[1]), "r"(a[2]), "r"(a[3]), "r"(b[0]), "r"(b[1]));
}
// pack (x->low16, y->high16) as bf16x2, plus residual pack
__device__ __forceinline__ void split_pack(float x, float y, unsigned& hp, unsigned& lp) {
    bf16 xh = __float2bfloat16(x), yh = __float2bfloat16(y);
    hp = ((unsigned)__bfloat16_as_ushort(yh) << 16) | (unsigned)__bfloat16_as_ushort(xh);
    bf16 xl = __float2bfloat16(x - __bfloat162float(xh));
    bf16 yl = __float2bfloat16(y - __bfloat162float(yh));
    lp = ((unsigned)__bfloat16_as_ushort(yl) << 16) | (unsigned)__bfloat16_as_ushort(xl);
}

// ---------------- RoPE tables ----------------
__global__ void build_tables_kernel(const int* __restrict__ positions) {
    int idx = blockIdx.x * blockDim.x + threadIdx.x;
    if (idx >= SS * HALF) return;
    int s = idx >> 6, i = idx & 63;
    double inv = pow(10000.0, -((double)(2 * i)) / (double)DD);
    double ang = (double)positions[s] * inv;
    g_cos[idx] = (float)cos(ang);
    g_sin[idx] = (float)sin(ang);
}

// ---------------- elementwise fp32 -> bf16 hi/lo ----------------
__global__ void cvt_split_kernel(const float* __restrict__ src, bf16* __restrict__ dh,
                                 bf16* __restrict__ dl, size_t n) {
    size_t i = (size_t)blockIdx.x * blockDim.x + threadIdx.x;
    if (i >= n) return;
    float x = src[i];
    bf16 h = __float2bfloat16(x);
    dh[i] = h;
    dl[i] = __float2bfloat16(x - __bfloat162float(h));
}

// ---------------- transpose + split: src [R][C] f32 -> dst [C][R] bf16 hi/lo ----
__global__ void transpose_cvt_kernel(const float* __restrict__ src, int R, int C,
                                     bf16* __restrict__ dh, bf16* __restrict__ dl) {
    __shared__ float t[32][33];
    int c0 = blockIdx.x * 32, r0 = blockIdx.y * 32;
    for (int i = threadIdx.y; i < 32; i += 8)
        t[i][threadIdx.x] = src[(size_t)(r0 + i) * C + c0 + threadIdx.x];
    __syncthreads();
    for (int i = threadIdx.y; i < 32; i += 8) {
        float x = t[threadIdx.x][i];
        bf16 h = __float2bfloat16(x);
        size_t o = (size_t)(c0 + i) * R + r0 + threadIdx.x;
        dh[o] = h;
        dl[o] = __float2bfloat16(x - __bfloat162float(h));
    }
}

// ---------------- V transpose+split: qkv -> vT [b,kh,d,s] ----------------
__global__ void v_transpose_kernel() {
    __shared__ float t[32][33];
    int s0 = blockIdx.x * 32, d0 = blockIdx.y * 32;
    int bk = blockIdx.z;            // b*NKVH + kh
    int b = bk / NKVH, kh = bk % NKVH;
    const float* src = g_qkv + (size_t)(b * SS) * CQKV + (NHD * DD + NKVH * DD) + kh * DD;
    for (int i = threadIdx.y; i < 32; i += 8)
        t[i][threadIdx.x] = src[(size_t)(s0 + i) * CQKV + d0 + threadIdx.x];
    __syncthreads();
    bf16* dh = g_vth + (size_t)bk * DD * SS;
    bf16* dl = g_vtl + (size_t)bk * DD * SS;
    for (int i = threadIdx.y; i < 32; i += 8) {
        float x = t[threadIdx.x][i];
        bf16 h = __float2bfloat16(x);
        size_t o = (size_t)(d0 + i) * SS + s0 + threadIdx.x;
        dh[o] = h;
        dl[o] = __float2bfloat16(x - __bfloat162float(h));
    }
}

// ---------------- RoPE + scatter (q,k) ----------------
__global__ void rope_scatter_kernel() {
    const int m = blockIdx.x;   // b*S + s
    const int b = m / SS, s = m % SS;
    const float* row = g_qkv + (size_t)m * CQKV;
    const float* ct = g_cos + s * HALF;
    const float* st = g_sin + s * HALF;

    for (int idx = threadIdx.x; idx < NHD * HALF; idx += blockDim.x) {
        int h = idx >> 6, i = idx & 63;
        float x1 = row[h * DD + i], x2 = row[h * DD + i + HALF];
        float c = ct[i], sn = st[i];
        float v1 = (x1 * c - x2 * sn) * SCALE;
        float v2 = (x2 * c + x1 * sn) * SCALE;
        size_t base = ((size_t)(b * NHD + h) * SS + s) * DD;
        bf16 h1 = __float2bfloat16(v1), h2 = __float2bfloat16(v2);
        g_qh[base + i] = h1;
        g_qh[base + i + HALF] = h2;
        g_ql[base + i] = __float2bfloat16(v1 - __bfloat162float(h1));
        g_ql[base + i + HALF] = __float2bfloat16(v2 - __bfloat162float(h2));
    }
    for (int idx = threadIdx.x; idx < NKVH * HALF; idx += blockDim.x) {
        int h = idx >> 6, i = idx & 63;
        float x1 = row[NHD * DD + h * DD + i], x2 = row[NHD * DD + h * DD + i + HALF];
        float c = ct[i], sn = st[i];
        float v1 = x1 * c - x2 * sn;
        float v2 = x2 * c + x1 * sn;
        size_t base = ((size_t)(b * NKVH + h) * SS + s) * DD;
        bf16 h1 = __float2bfloat16(v1), h2 = __float2bfloat16(v2);
        g_kh[base + i] = h1;
        g_kh[base + i + HALF] = h2;
        g_kl[base + i] = __float2bfloat16(v1 - __bfloat162float(h1));
        g_kl[base + i + HALF] = __float2bfloat16(v2 - __bfloat162float(h2));
    }
}

// ---------------- split-bf16 GEMM ----------------
// C[M][N] = sum_k A[m][k]*B[n][k], A = Ah+Al [M][K] bf16, B = Bh+Bl [N][K] bf16.
// 128x128x32 tiles, 2-stage cp.async, 256 thr (8 warps, 2x4, warp tile 64x32).
#define PW 20            // smem words per row (32 halfs = 16 words + 4 pad)
#define TW (128*PW)      // 2560 words per tile array
#define GEMM_SMEM (8*TW*4)

__global__ __launch_bounds__(256, 1)
void gemm_split_kernel(int M, int N, int K,
                       const bf16* __restrict__ Ah, const bf16* __restrict__ Al,
                       const bf16* __restrict__ Bh, const bf16* __restrict__ Bl,
                       float* __restrict__ C) {
    extern __shared__ unsigned sw[];
    const unsigned smemBase = (unsigned)__cvta_generic_to_shared(sw);

    const int tid = threadIdx.x;
    const int wid = tid >> 5, lane = tid & 31;
    const int g = lane >> 2, tg = lane & 3;
    const int wm = wid >> 2, wn = wid & 3;   // 2 x 4 warp grid
    const size_t brow = (size_t)blockIdx.y * 128;
    const size_t bcol = (size_t)blockIdx.x * 128;

    const int lr = tid >> 1, lh = tid & 1;
    const bf16* sAh = Ah + (brow + lr) * (size_t)K + lh * 16;
    const bf16* sAl = Al + (brow + lr) * (size_t)K + lh * 16;
    const bf16* sBh = Bh + (bcol + lr) * (size_t)K + lh * 16;
    const bf16* sBl = Bl + (bcol + lr) * (size_t)K + lh * 16;
    const unsigned soff = (lr * PW + lh * 8) * 4;

#define GISSUE(st, k0) {                                                     \
        unsigned a0 = smemBase + ((st) * TW) * 4 + soff;                     \
        cpa16(a0, sAh + (k0)); cpa16(a0 + 16, sAh + (k0) + 8);               \
        unsigned a1 = smemBase + ((2 + (st)) * TW) * 4 + soff;               \
        cpa16(a1, sAl + (k0)); cpa16(a1 + 16, sAl + (k0) + 8);               \
        unsigned a2 = smemBase + ((4 + (st)) * TW) * 4 + soff;               \
        cpa16(a2, sBh + (k0)); cpa16(a2 + 16, sBh + (k0) + 8);               \
        unsigned a3 = smemBase + ((6 + (st)) * TW) * 4 + soff;               \
        cpa16(a3, sBl + (k0)); cpa16(a3 + 16, sBl + (k0) + 8);               \
    }

    float acc[4][4][4];
#pragma unroll
    for (int mt = 0; mt < 4; mt++)
#pragma unroll
        for (int nt = 0; nt < 4; nt++)
#pragma unroll
            for (int i = 0; i < 4; i++) acc[mt][nt][i] = 0.f;

    const int nIter = K / 32;
    GISSUE(0, 0); cpa_commit();

    for (int it = 0; it < nIter; it++) {
        if (it + 1 < nIter) { GISSUE((it + 1) & 1, (it + 1) * 32); cpa_commit(); cpa_wait<1>(); }
        else                { cpa_wait<0>(); }
        __syncthreads();

        const int st = it & 1;
        const unsigned* As_h = sw + st * TW;
        const unsigned* As_l = sw + (2 + st) * TW;
        const unsigned* Bs_h = sw + (4 + st) * TW;
        const unsigned* Bs_l = sw + (6 + st) * TW;

#pragma unroll
        for (int ks = 0; ks < 2; ks++) {
            const int kw = ks * 8;
            unsigned ah[4][4], al[4][4], bh[4][2], bl[4][2];
#pragma unroll
            for (int nt = 0; nt < 4; nt++) {
                int nb = (wn * 32 + nt * 8 + g) * PW + kw + tg;
                bh[nt][0] = Bs_h[nb]; bh[nt][1] = Bs_h[nb + 4];
                bl[nt][0] = Bs_l[nb]; bl[nt][1] = Bs_l[nb + 4];
            }
#pragma unroll
            for (int mt = 0; mt < 4; mt++) {
                int mb = (wm * 64 + mt * 16 + g) * PW + kw + tg;
                ah[mt][0] = As_h[mb];          ah[mt][1] = As_h[mb + 8 * PW];
                ah[mt][2] = As_h[mb + 4];      ah[mt][3] = As_h[mb + 8 * PW + 4];
                al[mt][0] = As_l[mb];          al[mt][1] = As_l[mb + 8 * PW];
                al[mt][2] = As_l[mb + 4];      al[mt][3] = As_l[mb + 8 * PW + 4];
            }
#pragma unroll
            for (int mt = 0; mt < 4; mt++)
#pragma unroll
                for (int nt = 0; nt < 4; nt++) mma16(acc[mt][nt], ah[mt], bh[nt]);
#pragma unroll
            for (int mt = 0; mt < 4; mt++)
#pragma unroll
                for (int nt = 0; nt < 4; nt++) mma16(acc[mt][nt], ah[mt], bl[nt]);
#pragma unroll
            for (int mt = 0; mt < 4; mt++)
#pragma unroll
                for (int nt = 0; nt < 4; nt++) mma16(acc[mt][nt], al[mt], bh[nt]);
        }
        __syncthreads();
    }

#pragma unroll
    for (int mt = 0; mt < 4; mt++)
#pragma unroll
        for (int nt = 0; nt < 4; nt++) {
            size_t row = brow + wm * 64 + mt * 16 + g;
            size_t col = bcol + wn * 32 + nt * 8 + 2 * tg;
            *(float2*)(C + row * N + col) = make_float2(acc[mt][nt][0], acc[mt][nt][1]);
            *(float2*)(C + (row + 8) * N + col) = make_float2(acc[mt][nt][2], acc[mt][nt][3]);
        }
#undef GISSUE
}

// ---------------- Flash attention (split-bf16 mma) ----------------
// Block = 64 q rows, 4 warps (16 rows each). KV tile 64, double-buffered.
#define KQP 68   // words per Q/K row (128 halfs = 64 words + 4 pad)
#define VP  36   // words per V row (64 halfs = 32 words + 4 pad)
#define FQW 4352           // 64*KQP
#define FVW 4608           // 128*VP
// layout (words): QH 0, QL 4352, KH[st] 8704+st*4352, KL[st]=KH+8704,
//                 VH[st] 26112+st*4608, VL[st]=VH+9216
#define FLASH_SMEM (44544*4)

__global__ __launch_bounds__(128, 1)
void flash3_kernel() {
    extern __shared__ unsigned sw[];
    const unsigned smemBase = (unsigned)__cvta_generic_to_shared(sw);

    const int bx = blockIdx.x, h = blockIdx.y, b = blockIdx.z;
    const int tid = threadIdx.x, wid = tid >> 5, lane = tid & 31;
    const int g = lane >> 2, tg = lane & 3;
    const int qbase = bx * 64;
    const int kh = h >> 2;

    const int lr = tid >> 1, lh = tid & 1;
    const size_t qrow0 = ((size_t)(b * NHD + h) * SS + qbase + lr) * DD + lh * 64;
    const size_t krowB = (size_t)(b * NKVH + kh) * SS;
    const size_t vrow0 = ((size_t)(b * NKVH + kh) * DD + tid) * SS;

    // issue Q (once)
    {
        const bf16* sQh = g_qh + qrow0;
        const bf16* sQl = g_ql + qrow0;
        unsigned dq = smemBase + (lr * KQP + lh * 32) * 4;
#pragma unroll
        for (int j = 0; j < 8; j++) {
            cpa16(dq + j * 16, sQh + j * 8);
            cpa16(dq + FQW * 4 + j * 16, sQl + j * 8);
        }
    }
#define FISSUE_KV(t, st) {                                                    \
        const bf16* sKh = g_kh + (krowB + (t) * 64 + lr) * DD + lh * 64;      \
        const bf16* sKl = g_kl + (krowB + (t) * 64 + lr) * DD + lh * 64;      \
        unsigned dk = smemBase + ((8704 + (st) * 4352) + lr * KQP + lh * 32) * 4; \
        _Pragma("unroll")                                                     \
        for (int j = 0; j < 8; j++) {                                         \
            cpa16(dk + j * 16, sKh + j * 8);                                  \
            cpa16(dk + 8704 * 4 + j * 16, sKl + j * 8);                       \
        }                                                                     \
        const bf16* sVh = g_vth + vrow0 + (t) * 64;                           \
        const bf16* sVl = g_vtl + vrow0 + (t) * 64;                           \
        unsigned dv = smemBase + ((26112 + (st) * 4608) + tid * VP) * 4;      \
        _Pragma("unroll")                                                     \
        for (int j = 0; j < 8; j++) {                                         \
            cpa16(dv + j * 16, sVh + j * 8);                                  \
            cpa16(dv + 9216 * 4 + j * 16, sVl + j * 8);                       \
        }                                                                     \
    }

    FISSUE_KV(0, 0); cpa_commit();

    float Oacc[16][4];
#pragma unroll
    for (int nt = 0; nt < 16; nt++)
#pragma unroll
        for (int i = 0; i < 4; i++) Oacc[nt][i] = 0.f;
    float m0 = -1e30f, m1 = -1e30f, l0 = 0.f, l1 = 0.f;

    const unsigned* Qsh = sw;
    const unsigned* Qsl = sw + FQW;

    int st = 0;
    for (int t = 0; t <= bx; t++) {
        if (t < bx) { FISSUE_KV(t + 1, st ^ 1); cpa_commit(); cpa_wait<1>(); }
        else        { cpa_wait<0>(); }
        __syncthreads();

        const unsigned* Ksh = sw + 8704 + st * 4352;
        const unsigned* Ksl = Ksh + 8704;
        const unsigned* Vsh = sw + 26112 + st * 4608;
        const unsigned* Vsl = Vsh + 9216;

        // ---- scores: S(16x64 per warp) = Q @ K^T, 3-pass split-bf16
        float sacc[8][4];
#pragma unroll
        for (int nt = 0; nt < 8; nt++)
#pragma unroll
            for (int i = 0; i < 4; i++) sacc[nt][i] = 0.f;

        const int qw0 = (wid * 16 + g) * KQP;
#pragma unroll
        for (int ks = 0; ks < 8; ks++) {
            const int kw = ks * 8 + tg;
            unsigned ah[4], al[4], bh[8][2], bl[8][2];
            ah[0] = Qsh[qw0 + kw];            ah[1] = Qsh[qw0 + 8 * KQP + kw];
            ah[2] = Qsh[qw0 + kw + 4];        ah[3] = Qsh[qw0 + 8 * KQP + kw + 4];
            al[0] = Qsl[qw0 + kw];            al[1] = Qsl[qw0 + 8 * KQP + kw];
            al[2] = Qsl[qw0 + kw + 4];        al[3] = Qsl[qw0 + 8 * KQP + kw + 4];
#pragma unroll
            for (int nt = 0; nt < 8; nt++) {
                int kb = (nt * 8 + g) * KQP + kw;
                bh[nt][0] = Ksh[kb]; bh[nt][1] = Ksh[kb + 4];
                bl[nt][0] = Ksl[kb]; bl[nt][1] = Ksl[kb + 4];
            }
#pragma unroll
            for (int nt = 0; nt < 8; nt++) mma16(sacc[nt], ah, bh[nt]);
#pragma unroll
            for (int nt = 0; nt < 8; nt++) mma16(sacc[nt], ah, bl[nt]);
#pragma unroll
            for (int nt = 0; nt < 8; nt++) mma16(sacc[nt], al, bh[nt]);
        }

        // ---- causal mask (diagonal tile only)
        if (t == bx) {
            int r0 = qbase + wid * 16 + g, r1 = r0 + 8;
#pragma unroll
            for (int nt = 0; nt < 8; nt++) {
                int c0 = t * 64 + nt * 8 + 2 * tg, c1 = c0 + 1;
                if (c0 > r0) sacc[nt][0] = -1e30f;
                if (c1 > r0) sacc[nt][1] = -1e30f;
                if (c0 > r1) sacc[nt][2] = -1e30f;
                if (c1 > r1) sacc[nt][3] = -1e30f;
            }
        }

        // ---- online softmax
        float tm0 = -1e30f, tm1 = -1e30f;
#pragma unroll
        for (int nt = 0; nt < 8; nt++) {
            tm0 = fmaxf(tm0, fmaxf(sacc[nt][0], sacc[nt][1]));
            tm1 = fmaxf(tm1, fmaxf(sacc[nt][2], sacc[nt][3]));
        }
        tm0 = fmaxf(tm0, __shfl_xor_sync(0xffffffffu, tm0, 1));
        tm0 = fmaxf(tm0, __shfl_xor_sync(0xffffffffu, tm0, 2));
        tm1 = fmaxf(tm1, __shfl_xor_sync(0xffffffffu, tm1, 1));
        tm1 = fmaxf(tm1, __shfl_xor_sync(0xffffffffu, tm1, 2));

        float mn0 = fmaxf(m0, tm0), mn1 = fmaxf(m1, tm1);
        float a0 = __expf(m0 - mn0), a1 = __expf(m1 - mn1);
        l0 *= a0; l1 *= a1;
#pragma unroll
        for (int nt = 0; nt < 16; nt++) {
            Oacc[nt][0] *= a0; Oacc[nt][1] *= a0;
            Oacc[nt][2] *= a1; Oacc[nt][3] *= a1;
        }

        float p0a[8], p1a[8], p2a[8], p3a[8];
        float rs0 = 0.f, rs1 = 0.f;
#pragma unroll
        for (int nt = 0; nt < 8; nt++) {
            p0a[nt] = __expf(sacc[nt][0] - mn0);
            p1a[nt] = __expf(sacc[nt][1] - mn0);
            p2a[nt] = __expf(sacc[nt][2] - mn1);
            p3a[nt] = __expf(sacc[nt][3] - mn1);
            rs0 += p0a[nt] + p1a[nt];
            rs1 += p2a[nt] + p3a[nt];
        }
        rs0 += __shfl_xor_sync(0xffffffffu, rs0, 1);
        rs0 += __shfl_xor_sync(0xffffffffu, rs0, 2);
        rs1 += __shfl_xor_sync(0xffffffffu, rs1, 1);
        rs1 += __shfl_xor_sync(0xffffffffu, rs1, 2);
        l0 += rs0; l1 += rs1;
        m0 = mn0; m1 = mn1;

        // ---- PV: O(16x128 per warp) += P(16x64) @ V, 3-pass split-bf16
#pragma unroll
        for (int ks = 0; ks < 4; ks++) {
            unsigned aH[4], aL[4];
            split_pack(p0a[2 * ks],     p1a[2 * ks],     aH[0], aL[0]);
            split_pack(p2a[2 * ks],     p3a[2 * ks],     aH[1], aL[1]);
            split_pack(p0a[2 * ks + 1], p1a[2 * ks + 1], aH[2], aL[2]);
            split_pack(p2a[2 * ks + 1], p3a[2 * ks + 1], aH[3], aL[3]);
#pragma unroll
            for (int hf = 0; hf < 2; hf++) {
                unsigned vbh[8][2], vbl[8][2];
#pragma unroll
                for (int i = 0; i < 8; i++) {
                    int vw = ((hf * 8 + i) * 8 + g) * VP + ks * 8 + tg;
                    vbh[i][0] = Vsh[vw]; vbh[i][1] = Vsh[vw + 4];
                    vbl[i][0] = Vsl[vw]; vbl[i][1] = Vsl[vw + 4];
                }
#pragma unroll
                for (int i = 0; i < 8; i++) mma16(Oacc[hf * 8 + i], aH, vbh[i]);
#pragma unroll
                for (int i = 0; i < 8; i++) mma16(Oacc[hf * 8 + i], aH, vbl[i]);
#pragma unroll
                for (int i = 0; i < 8; i++) mma16(Oacc[hf * 8 + i], aL, vbh[i]);
            }
        }
        __syncthreads();
        st ^= 1;
    }

    // ---- epilogue: O hi/lo bf16 to g_oh/g_ol
    float inv0 = 1.f / l0, inv1 = 1.f / l1;
    int r0 = qbase + wid * 16 + g;
    size_t ro0 = ((size_t)(b * SS) + r0) * (NHD * DD) + h * DD;
    size_t ro1 = ((size_t)(b * SS) + r0 + 8) * (NHD * DD) + h * DD;
#pragma unroll
    for (int nt = 0; nt < 16; nt++) {
        int c = nt * 8 + 2 * tg;
        float o0 = Oacc[nt][0] * inv0, o1 = Oacc[nt][1] * inv0;
        float o2 = Oacc[nt][2] * inv1, o3 = Oacc[nt][3] * inv1;
        unsigned hp, lp;
        split_pack(o0, o1, hp, lp);
        *(unsigned*)(g_oh + ro0 + c) = hp;
        *(unsigned*)(g_ol + ro0 + c) = lp;
        split_pack(o2, o3, hp, lp);
        *(unsigned*)(g_oh + ro1 + c) = hp;
        *(unsigned*)(g_ol + ro1 + c) = lp;
    }
#undef FISSUE_KV
}

// ---------------- launch ----------------
extern "C" void kernel_launch(void* const* d_in, const int* in_sizes, int n_in,
                              void* d_out, int out_size) {
    const int*   positions = (const int*)d_in[0];
    const float* hidden    = (const float*)d_in[1];
    const float* w_qkv     = (const float*)d_in[2];
    const float* w_o       = (const float*)d_in[3];
    float*       out       = (float*)d_out;

    float *qkv;
    bf16 *hidh, *hidl, *wqTh, *wqTl, *woTh, *woTl, *oh, *ol;
    cudaGetSymbolAddress((void**)&qkv,  g_qkv);
    cudaGetSymbolAddress((void**)&hidh, g_hidh);
    cudaGetSymbolAddress((void**)&hidl, g_hidl);
    cudaGetSymbolAddress((void**)&wqTh, g_wqTh);
    cudaGetSymbolAddress((void**)&wqTl, g_wqTl);
    cudaGetSymbolAddress((void**)&woTh, g_woTh);
    cudaGetSymbolAddress((void**)&woTl, g_woTl);
    cudaGetSymbolAddress((void**)&oh,   g_oh);
    cudaGetSymbolAddress((void**)&ol,   g_ol);

    cudaFuncSetAttribute(gemm_split_kernel,
                         cudaFuncAttributeMaxDynamicSharedMemorySize, GEMM_SMEM);
    cudaFuncSetAttribute(flash3_kernel,
                         cudaFuncAttributeMaxDynamicSharedMemorySize, FLASH_SMEM);

    // 1) RoPE tables + operand conversions
    build_tables_kernel<<<(SS * HALF + 255) / 256, 256>>>(positions);
    cvt_split_kernel<<<(unsigned)(((size_t)MM * HH + 255) / 256), 256>>>(
        hidden, hidh, hidl, (size_t)MM * HH);
    {
        dim3 grid(CQKV / 32, HH / 32); dim3 blk(32, 8);
        transpose_cvt_kernel<<<grid, blk>>>(w_qkv, HH, CQKV, wqTh, wqTl);
    }
    {
        dim3 grid(HH / 32, HH / 32); dim3 blk(32, 8);
        transpose_cvt_kernel<<<grid, blk>>>(w_o, HH, HH, woTh, woTl);
    }

    // 2) QKV GEMM
    {
        dim3 grid(CQKV / 128, MM / 128);
        gemm_split_kernel<<<grid, 256, GEMM_SMEM>>>(MM, CQKV, HH,
                                                    hidh, hidl, wqTh, wqTl, qkv);
    }

    // 3) RoPE + scatter (q,k) and V transpose
    rope_scatter_kernel<<<MM, 256>>>();
    {
        dim3 grid(SS / 32, DD / 32, BB * NKVH); dim3 blk(32, 8);
        v_transpose_kernel<<<grid, blk>>>();
    }

    // 4) Flash attention
    {
        dim3 grid(SS / 64, NHD, BB);
        flash3_kernel<<<grid, 128, FLASH_SMEM>>>();
    }

    // 5) Output projection
    {
        dim3 grid(HH / 128, MM / 128);
        gemm_split_kernel<<<grid, 256, GEMM_SMEM>>>(MM, HH, HH,
                                                    oh, ol, woTh, woTl, out);
    }
}

// round 8
// speedup vs baseline: 5.5808x; 1.2113x over previous
#include <cuda_runtime.h>
#include <cuda_bf16.h>
#include <math.h>
#include <stdint.h>

#define BB   2
#define SS   2048
#define HH   4096
#define NHD  32
#define NKVH 8
#define DD   128
#define CQKV 6144
#define MM   (BB*SS)         // 4096
#define HALF 64
#define SCALE 0.08838834764831843f

typedef __nv_bfloat16 bf16;

// ---------------- device scratch (allocation-free) ----------------
__device__ float g_qkv [(size_t)MM*CQKV];
__device__ bf16  g_hidh[(size_t)MM*HH],    g_hidl[(size_t)MM*HH];
__device__ bf16  g_wqTh[(size_t)CQKV*HH],  g_wqTl[(size_t)CQKV*HH];
__device__ bf16  g_woTh[(size_t)HH*HH],    g_woTl[(size_t)HH*HH];
__device__ bf16  g_qh[(size_t)BB*NHD*SS*DD],  g_ql[(size_t)BB*NHD*SS*DD];
__device__ bf16  g_kh[(size_t)BB*NKVH*SS*DD], g_kl[(size_t)BB*NKVH*SS*DD];
__device__ bf16  g_vth[(size_t)BB*NKVH*DD*SS], g_vtl[(size_t)BB*NKVH*DD*SS];
__device__ bf16  g_oh[(size_t)MM*HH],      g_ol[(size_t)MM*HH];
__device__ float g_cos[SS*HALF], g_sin[SS*HALF];

// ---------------- helpers ----------------
__device__ __forceinline__ void cpa16(unsigned d, const void* s) {
    asm volatile("cp.async.ca.shared.global [%0], [%1], 16;" :: "r"(d), "l"(s));
}
__device__ __forceinline__ void cpa_commit() {
    asm volatile("cp.async.commit_group;");
}
template<int N>
__device__ __forceinline__ void cpa_wait() {
    asm volatile("cp.async.wait_group %0;" :: "n"(N));
}
__device__ __forceinline__ void mma16(float* c, const unsigned* a, const unsigned* b) {
    asm volatile(
        "mma.sync.aligned.m16n8k16.row.col.f32.bf16.bf16.f32 "
        "{%0,%1,%2,%3}, {%4,%5,%6,%7}, {%8,%9}, {%0,%1,%2,%3};"
        : "+f"(c[0]), "+f"(c[1]), "+f"(c[2]), "+f"(c[3])
        : "r"(a[0]), "r"(a[1]), "r"(a[2]), "r"(a[3]), "r"(b[0]), "r"(b[1]));
}
__device__ __forceinline__ void ldm4(unsigned* r, unsigned addr) {
    asm volatile("ldmatrix.sync.aligned.m8n8.x4.shared.b16 {%0,%1,%2,%3}, [%4];"
        : "=r"(r[0]), "=r"(r[1]), "=r"(r[2]), "=r"(r[3]) : "r"(addr));
}
__device__ __forceinline__ void split_pack(float x, float y, unsigned& hp, unsigned& lp) {
    bf16 xh = __float2bfloat16(x), yh = __float2bfloat16(y);
    hp = ((unsigned)__bfloat16_as_ushort(yh) << 16) | (unsigned)__bfloat16_as_ushort(xh);
    bf16 xl = __float2bfloat16(x - __bfloat162float(xh));
    bf16 yl = __float2bfloat16(y - __bfloat162float(yh));
    lp = ((unsigned)__bfloat16_as_ushort(yl) << 16) | (unsigned)__bfloat16_as_ushort(xl);
}

// ---------------- RoPE tables ----------------
__global__ void build_tables_kernel(const int* __restrict__ positions) {
    int idx = blockIdx.x * blockDim.x + threadIdx.x;
    if (idx >= SS * HALF) return;
    int s = idx >> 6, i = idx & 63;
    double inv = pow(10000.0, -((double)(2 * i)) / (double)DD);
    double ang = (double)positions[s] * inv;
    g_cos[idx] = (float)cos(ang);
    g_sin[idx] = (float)sin(ang);
}

// ---------------- elementwise fp32 -> bf16 hi/lo ----------------
__global__ void cvt_split_kernel(const float* __restrict__ src, bf16* __restrict__ dh,
                                 bf16* __restrict__ dl, size_t n) {
    size_t i = (size_t)blockIdx.x * blockDim.x + threadIdx.x;
    if (i >= n) return;
    float x = src[i];
    bf16 h = __float2bfloat16(x);
    dh[i] = h;
    dl[i] = __float2bfloat16(x - __bfloat162float(h));
}

// ---------------- transpose + split ----------------
__global__ void transpose_cvt_kernel(const float* __restrict__ src, int R, int C,
                                     bf16* __restrict__ dh, bf16* __restrict__ dl) {
    __shared__ float t[32][33];
    int c0 = blockIdx.x * 32, r0 = blockIdx.y * 32;
    for (int i = threadIdx.y; i < 32; i += 8)
        t[i][threadIdx.x] = src[(size_t)(r0 + i) * C + c0 + threadIdx.x];
    __syncthreads();
    for (int i = threadIdx.y; i < 32; i += 8) {
        float x = t[threadIdx.x][i];
        bf16 h = __float2bfloat16(x);
        size_t o = (size_t)(c0 + i) * R + r0 + threadIdx.x;
        dh[o] = h;
        dl[o] = __float2bfloat16(x - __bfloat162float(h));
    }
}

// ---------------- V transpose+split ----------------
__global__ void v_transpose_kernel() {
    __shared__ float t[32][33];
    int s0 = blockIdx.x * 32, d0 = blockIdx.y * 32;
    int bk = blockIdx.z;
    int b = bk / NKVH, kh = bk % NKVH;
    const float* src = g_qkv + (size_t)(b * SS) * CQKV + (NHD * DD + NKVH * DD) + kh * DD;
    for (int i = threadIdx.y; i < 32; i += 8)
        t[i][threadIdx.x] = src[(size_t)(s0 + i) * CQKV + d0 + threadIdx.x];
    __syncthreads();
    bf16* dh = g_vth + (size_t)bk * DD * SS;
    bf16* dl = g_vtl + (size_t)bk * DD * SS;
    for (int i = threadIdx.y; i < 32; i += 8) {
        float x = t[threadIdx.x][i];
        bf16 h = __float2bfloat16(x);
        size_t o = (size_t)(d0 + i) * SS + s0 + threadIdx.x;
        dh[o] = h;
        dl[o] = __float2bfloat16(x - __bfloat162float(h));
    }
}

// ---------------- RoPE + scatter (q,k) ----------------
__global__ void rope_scatter_kernel() {
    const int m = blockIdx.x;
    const int b = m / SS, s = m % SS;
    const float* row = g_qkv + (size_t)m * CQKV;
    const float* ct = g_cos + s * HALF;
    const float* st = g_sin + s * HALF;

    for (int idx = threadIdx.x; idx < NHD * HALF; idx += blockDim.x) {
        int h = idx >> 6, i = idx & 63;
        float x1 = row[h * DD + i], x2 = row[h * DD + i + HALF];
        float c = ct[i], sn = st[i];
        float v1 = (x1 * c - x2 * sn) * SCALE;
        float v2 = (x2 * c + x1 * sn) * SCALE;
        size_t base = ((size_t)(b * NHD + h) * SS + s) * DD;
        bf16 h1 = __float2bfloat16(v1), h2 = __float2bfloat16(v2);
        g_qh[base + i] = h1;
        g_qh[base + i + HALF] = h2;
        g_ql[base + i] = __float2bfloat16(v1 - __bfloat162float(h1));
        g_ql[base + i + HALF] = __float2bfloat16(v2 - __bfloat162float(h2));
    }
    for (int idx = threadIdx.x; idx < NKVH * HALF; idx += blockDim.x) {
        int h = idx >> 6, i = idx & 63;
        float x1 = row[NHD * DD + h * DD + i], x2 = row[NHD * DD + h * DD + i + HALF];
        float c = ct[i], sn = st[i];
        float v1 = x1 * c - x2 * sn;
        float v2 = x2 * c + x1 * sn;
        size_t base = ((size_t)(b * NKVH + h) * SS + s) * DD;
        bf16 h1 = __float2bfloat16(v1), h2 = __float2bfloat16(v2);
        g_kh[base + i] = h1;
        g_kh[base + i + HALF] = h2;
        g_kl[base + i] = __float2bfloat16(v1 - __bfloat162float(h1));
        g_kl[base + i + HALF] = __float2bfloat16(v2 - __bfloat162float(h2));
    }
}

// ---------------- split-bf16 GEMM (HMMA + ldmatrix) ----------------
// C[M][N] = sum_k (Ah+Al)[m][k] * (Bh+Bl)[n][k], 3-pass split.
// 128x128x32 tiles, 2-stage cp.async, 256 thr (8 warps 2x4, warp tile 64x32).
#define PW 20            // smem words per row (32 halfs = 16 words + 4 pad)
#define TW (128*PW)
#define GEMM_SMEM (8*TW*4)

__global__ __launch_bounds__(256, 1)
void gemm_split_kernel(int M, int N, int K,
                       const bf16* __restrict__ Ah, const bf16* __restrict__ Al,
                       const bf16* __restrict__ Bh, const bf16* __restrict__ Bl,
                       float* __restrict__ C) {
    extern __shared__ unsigned sw[];
    const unsigned smemBase = (unsigned)__cvta_generic_to_shared(sw);

    const int tid = threadIdx.x;
    const int wid = tid >> 5, lane = tid & 31;
    const int g = lane >> 2, tg = lane & 3;
    const int wm = wid >> 2, wn = wid & 3;
    const size_t brow = (size_t)blockIdx.y * 128;
    const size_t bcol = (size_t)blockIdx.x * 128;

    const int lr = tid >> 1, lh = tid & 1;
    const bf16* sAh = Ah + (brow + lr) * (size_t)K + lh * 16;
    const bf16* sAl = Al + (brow + lr) * (size_t)K + lh * 16;
    const bf16* sBh = Bh + (bcol + lr) * (size_t)K + lh * 16;
    const bf16* sBl = Bl + (bcol + lr) * (size_t)K + lh * 16;
    const unsigned soff = (lr * PW + lh * 8) * 4;

    // ldmatrix invariant byte offsets
    const unsigned aoff = ((wm * 64 + (lane & 15)) * PW + ((lane & 16) ? 4 : 0)) * 4;
    const unsigned boff = ((wn * 32 + ((lane & 16) >> 1) + (lane & 7)) * PW
                           + ((lane & 8) ? 4 : 0)) * 4;

#define GISSUE(st, k0) {                                                     \
        unsigned a0 = smemBase + ((st) * TW) * 4 + soff;                     \
        cpa16(a0, sAh + (k0)); cpa16(a0 + 16, sAh + (k0) + 8);               \
        unsigned a1 = smemBase + ((2 + (st)) * TW) * 4 + soff;               \
        cpa16(a1, sAl + (k0)); cpa16(a1 + 16, sAl + (k0) + 8);               \
        unsigned a2 = smemBase + ((4 + (st)) * TW) * 4 + soff;               \
        cpa16(a2, sBh + (k0)); cpa16(a2 + 16, sBh + (k0) + 8);               \
        unsigned a3 = smemBase + ((6 + (st)) * TW) * 4 + soff;               \
        cpa16(a3, sBl + (k0)); cpa16(a3 + 16, sBl + (k0) + 8);               \
    }

    float acc[4][4][4];
#pragma unroll
    for (int mt = 0; mt < 4; mt++)
#pragma unroll
        for (int nt = 0; nt < 4; nt++)
#pragma unroll
            for (int i = 0; i < 4; i++) acc[mt][nt][i] = 0.f;

    const int nIter = K / 32;
    GISSUE(0, 0); cpa_commit();

    for (int it = 0; it < nIter; it++) {
        if (it + 1 < nIter) { GISSUE((it + 1) & 1, (it + 1) * 32); cpa_commit(); cpa_wait<1>(); }
        else                { cpa_wait<0>(); }
        __syncthreads();

        const int st = it & 1;
        const unsigned aHB = smemBase + (st * TW) * 4;
        const unsigned aLB = smemBase + ((2 + st) * TW) * 4;
        const unsigned bHB = smemBase + ((4 + st) * TW) * 4;
        const unsigned bLB = smemBase + ((6 + st) * TW) * 4;

#pragma unroll
        for (int ks = 0; ks < 2; ks++) {
            const unsigned kb = ks * 32;
            unsigned ah[4][4], al[4][4], bh[2][4], bl[2][4];
#pragma unroll
            for (int p = 0; p < 2; p++) {
                ldm4(bh[p], bHB + boff + p * 16 * PW * 4 + kb);
                ldm4(bl[p], bLB + boff + p * 16 * PW * 4 + kb);
            }
#pragma unroll
            for (int mt = 0; mt < 4; mt++) {
                ldm4(ah[mt], aHB + aoff + mt * 16 * PW * 4 + kb);
                ldm4(al[mt], aLB + aoff + mt * 16 * PW * 4 + kb);
            }
#pragma unroll
            for (int mt = 0; mt < 4; mt++)
#pragma unroll
                for (int nt = 0; nt < 4; nt++)
                    mma16(acc[mt][nt], ah[mt], &bh[nt >> 1][(nt & 1) * 2]);
#pragma unroll
            for (int mt = 0; mt < 4; mt++)
#pragma unroll
                for (int nt = 0; nt < 4; nt++)
                    mma16(acc[mt][nt], ah[mt], &bl[nt >> 1][(nt & 1) * 2]);
#pragma unroll
            for (int mt = 0; mt < 4; mt++)
#pragma unroll
                for (int nt = 0; nt < 4; nt++)
                    mma16(acc[mt][nt], al[mt], &bh[nt >> 1][(nt & 1) * 2]);
        }
        __syncthreads();
    }

#pragma unroll
    for (int mt = 0; mt < 4; mt++)
#pragma unroll
        for (int nt = 0; nt < 4; nt++) {
            size_t row = brow + wm * 64 + mt * 16 + g;
            size_t col = bcol + wn * 32 + nt * 8 + 2 * tg;
            *(float2*)(C + row * N + col) = make_float2(acc[mt][nt][0], acc[mt][nt][1]);
            *(float2*)(C + (row + 8) * N + col) = make_float2(acc[mt][nt][2], acc[mt][nt][3]);
        }
#undef GISSUE
}

// ---------------- Flash attention: 256 thr, 128 q-rows, ldmatrix ----------------
#define KQP 68   // Q/K row pitch in words (128 halfs + pad)
#define VP  36   // V row pitch in words (64 halfs + pad)
#define F_QH 0
#define F_QL 8704
#define F_KH(st) (17408 + (st)*4352)
#define F_KL(st) (26112 + (st)*4352)
#define F_VH(st) (34816 + (st)*4608)
#define F_VL(st) (44032 + (st)*4608)
#define FLASH_SMEM (53248*4)

__global__ __launch_bounds__(256, 1)
void flash4_kernel() {
    extern __shared__ unsigned sw[];
    const unsigned smemBase = (unsigned)__cvta_generic_to_shared(sw);

    const int bx = blockIdx.x, h = blockIdx.y, b = blockIdx.z;
    const int tid = threadIdx.x, wid = tid >> 5, lane = tid & 31;
    const int g = lane >> 2, tg = lane & 3;
    const int qbase = bx * 128;
    const int kh = h >> 2;

    // staging assignments
    const int qr = tid >> 1, qh2 = tid & 1;   // Q: row 0..127, half
    const int krow = tid >> 2, kq = tid & 3;  // K: row 0..63, quarter
    const int vrow = tid >> 1, vh2 = tid & 1; // V: d-row 0..127, half

    const size_t qg0 = ((size_t)(b * NHD + h) * SS + qbase + qr) * DD + qh2 * 64;
    const size_t krowB = (size_t)(b * NKVH + kh) * SS;
    const size_t vg0 = ((size_t)(b * NKVH + kh) * DD + vrow) * SS + vh2 * 32;

    // stage Q (once)
    {
        const bf16* sQh = g_qh + qg0;
        const bf16* sQl = g_ql + qg0;
        unsigned dq  = smemBase + (F_QH + qr * KQP + qh2 * 32) * 4;
        unsigned dql = smemBase + (F_QL + qr * KQP + qh2 * 32) * 4;
#pragma unroll
        for (int j = 0; j < 8; j++) {
            cpa16(dq  + j * 16, sQh + j * 8);
            cpa16(dql + j * 16, sQl + j * 8);
        }
    }
#define FKV(t, st) {                                                          \
        const bf16* sKh = g_kh + (krowB + (t) * 64 + krow) * DD + kq * 32;    \
        const bf16* sKl = g_kl + (krowB + (t) * 64 + krow) * DD + kq * 32;    \
        unsigned dk  = smemBase + (F_KH(st) + krow * KQP + kq * 16) * 4;      \
        unsigned dkl = smemBase + (F_KL(st) + krow * KQP + kq * 16) * 4;      \
        _Pragma("unroll")                                                     \
        for (int j = 0; j < 4; j++) {                                         \
            cpa16(dk  + j * 16, sKh + j * 8);                                 \
            cpa16(dkl + j * 16, sKl + j * 8);                                 \
        }                                                                     \
        const bf16* sVh = g_vth + vg0 + (t) * 64;                             \
        const bf16* sVl = g_vtl + vg0 + (t) * 64;                             \
        unsigned dv  = smemBase + (F_VH(st) + vrow * VP + vh2 * 16) * 4;      \
        unsigned dvl = smemBase + (F_VL(st) + vrow * VP + vh2 * 16) * 4;      \
        _Pragma("unroll")                                                     \
        for (int j = 0; j < 4; j++) {                                         \
            cpa16(dv  + j * 16, sVh + j * 8);                                 \
            cpa16(dvl + j * 16, sVl + j * 8);                                 \
        }                                                                     \
    }

    FKV(0, 0); cpa_commit();

    float Oacc[16][4];
#pragma unroll
    for (int nt = 0; nt < 16; nt++)
#pragma unroll
        for (int i = 0; i < 4; i++) Oacc[nt][i] = 0.f;
    float m0 = -1e30f, m1 = -1e30f, l0 = 0.f, l1 = 0.f;

    // ldmatrix invariant byte offsets
    const unsigned aoffQ = ((wid * 16 + (lane & 15)) * KQP + ((lane & 16) ? 4 : 0)) * 4;
    const unsigned boffK = ((((lane & 16) >> 1) + (lane & 7)) * KQP + ((lane & 8) ? 4 : 0)) * 4;
    const unsigned boffV = ((((lane & 16) >> 1) + (lane & 7)) * VP + ((lane & 8) ? 4 : 0)) * 4;
    const unsigned qHB = smemBase + F_QH * 4;
    const unsigned qLB = smemBase + F_QL * 4;

    const int ntile = 2 * bx + 2;
    int st = 0;
    for (int t = 0; t < ntile; t++) {
        if (t + 1 < ntile) { FKV(t + 1, st ^ 1); cpa_commit(); cpa_wait<1>(); }
        else               { cpa_wait<0>(); }
        __syncthreads();

        const unsigned kHB = smemBase + F_KH(st) * 4;
        const unsigned kLB = smemBase + F_KL(st) * 4;
        const unsigned vHB = smemBase + F_VH(st) * 4;
        const unsigned vLB = smemBase + F_VL(st) * 4;

        // ---- scores: S(16x64 per warp) = Q @ K^T, 3-pass split-bf16
        float sacc[8][4];
#pragma unroll
        for (int nt = 0; nt < 8; nt++)
#pragma unroll
            for (int i = 0; i < 4; i++) sacc[nt][i] = 0.f;

#pragma unroll
        for (int ks = 0; ks < 8; ks++) {
            const unsigned kb = ks * 32;
            unsigned ah[4], al[4], bh[4][4], bl[4][4];
            ldm4(ah, qHB + aoffQ + kb);
            ldm4(al, qLB + aoffQ + kb);
#pragma unroll
            for (int p = 0; p < 4; p++) {
                ldm4(bh[p], kHB + boffK + p * 16 * KQP * 4 + kb);
                ldm4(bl[p], kLB + boffK + p * 16 * KQP * 4 + kb);
            }
#pragma unroll
            for (int nt = 0; nt < 8; nt++)
                mma16(sacc[nt], ah, &bh[nt >> 1][(nt & 1) * 2]);
#pragma unroll
            for (int nt = 0; nt < 8; nt++)
                mma16(sacc[nt], ah, &bl[nt >> 1][(nt & 1) * 2]);
#pragma unroll
            for (int nt = 0; nt < 8; nt++)
                mma16(sacc[nt], al, &bh[nt >> 1][(nt & 1) * 2]);
        }

        // ---- causal mask (tiles overlapping the diagonal)
        if (t >= 2 * bx) {
            int r0 = qbase + wid * 16 + g, r1 = r0 + 8;
#pragma unroll
            for (int nt = 0; nt < 8; nt++) {
                int c0 = t * 64 + nt * 8 + 2 * tg, c1 = c0 + 1;
                if (c0 > r0) sacc[nt][0] = -1e30f;
                if (c1 > r0) sacc[nt][1] = -1e30f;
                if (c0 > r1) sacc[nt][2] = -1e30f;
                if (c1 > r1) sacc[nt][3] = -1e30f;
            }
        }

        // ---- online softmax
        float tm0 = -1e30f, tm1 = -1e30f;
#pragma unroll
        for (int nt = 0; nt < 8; nt++) {
            tm0 = fmaxf(tm0, fmaxf(sacc[nt][0], sacc[nt][1]));
            tm1 = fmaxf(tm1, fmaxf(sacc[nt][2], sacc[nt][3]));
        }
        tm0 = fmaxf(tm0, __shfl_xor_sync(0xffffffffu, tm0, 1));
        tm0 = fmaxf(tm0, __shfl_xor_sync(0xffffffffu, tm0, 2));
        tm1 = fmaxf(tm1, __shfl_xor_sync(0xffffffffu, tm1, 1));
        tm1 = fmaxf(tm1, __shfl_xor_sync(0xffffffffu, tm1, 2));

        float mn0 = fmaxf(m0, tm0), mn1 = fmaxf(m1, tm1);
        float a0 = __expf(m0 - mn0), a1 = __expf(m1 - mn1);
        l0 *= a0; l1 *= a1;
#pragma unroll
        for (int nt = 0; nt < 16; nt++) {
            Oacc[nt][0] *= a0; Oacc[nt][1] *= a0;
            Oacc[nt][2] *= a1; Oacc[nt][3] *= a1;
        }

        float p0a[8], p1a[8], p2a[8], p3a[8];
        float rs0 = 0.f, rs1 = 0.f;
#pragma unroll
        for (int nt = 0; nt < 8; nt++) {
            p0a[nt] = __expf(sacc[nt][0] - mn0);
            p1a[nt] = __expf(sacc[nt][1] - mn0);
            p2a[nt] = __expf(sacc[nt][2] - mn1);
            p3a[nt] = __expf(sacc[nt][3] - mn1);
            rs0 += p0a[nt] + p1a[nt];
            rs1 += p2a[nt] + p3a[nt];
        }
        rs0 += __shfl_xor_sync(0xffffffffu, rs0, 1);
        rs0 += __shfl_xor_sync(0xffffffffu, rs0, 2);
        rs1 += __shfl_xor_sync(0xffffffffu, rs1, 1);
        rs1 += __shfl_xor_sync(0xffffffffu, rs1, 2);
        l0 += rs0; l1 += rs1;
        m0 = mn0; m1 = mn1;

        // ---- PV: O(16x128 per warp) += P(16x64) @ V, 3-pass split-bf16
#pragma unroll
        for (int ks = 0; ks < 4; ks++) {
            const unsigned kb = ks * 32;
            unsigned aH[4], aL[4];
            split_pack(p0a[2 * ks],     p1a[2 * ks],     aH[0], aL[0]);
            split_pack(p2a[2 * ks],     p3a[2 * ks],     aH[1], aL[1]);
            split_pack(p0a[2 * ks + 1], p1a[2 * ks + 1], aH[2], aL[2]);
            split_pack(p2a[2 * ks + 1], p3a[2 * ks + 1], aH[3], aL[3]);
#pragma unroll
            for (int p = 0; p < 8; p++) {
                unsigned vbh[4], vbl[4];
                ldm4(vbh, vHB + boffV + p * 16 * VP * 4 + kb);
                ldm4(vbl, vLB + boffV + p * 16 * VP * 4 + kb);
                mma16(Oacc[2 * p],     aH, &vbh[0]);
                mma16(Oacc[2 * p + 1], aH, &vbh[2]);
                mma16(Oacc[2 * p],     aH, &vbl[0]);
                mma16(Oacc[2 * p + 1], aH, &vbl[2]);
                mma16(Oacc[2 * p],     aL, &vbh[0]);
                mma16(Oacc[2 * p + 1], aL, &vbh[2]);
            }
        }
        __syncthreads();
        st ^= 1;
    }

    // ---- epilogue: O hi/lo bf16
    float inv0 = 1.f / l0, inv1 = 1.f / l1;
    int r0 = qbase + wid * 16 + g;
    size_t ro0 = ((size_t)(b * SS) + r0) * (NHD * DD) + h * DD;
    size_t ro1 = ((size_t)(b * SS) + r0 + 8) * (NHD * DD) + h * DD;
#pragma unroll
    for (int nt = 0; nt < 16; nt++) {
        int c = nt * 8 + 2 * tg;
        float o0 = Oacc[nt][0] * inv0, o1 = Oacc[nt][1] * inv0;
        float o2 = Oacc[nt][2] * inv1, o3 = Oacc[nt][3] * inv1;
        unsigned hp, lp;
        split_pack(o0, o1, hp, lp);
        *(unsigned*)(g_oh + ro0 + c) = hp;
        *(unsigned*)(g_ol + ro0 + c) = lp;
        split_pack(o2, o3, hp, lp);
        *(unsigned*)(g_oh + ro1 + c) = hp;
        *(unsigned*)(g_ol + ro1 + c) = lp;
    }
#undef FKV
}

// ---------------- launch ----------------
extern "C" void kernel_launch(void* const* d_in, const int* in_sizes, int n_in,
                              void* d_out, int out_size) {
    const int*   positions = (const int*)d_in[0];
    const float* hidden    = (const float*)d_in[1];
    const float* w_qkv     = (const float*)d_in[2];
    const float* w_o       = (const float*)d_in[3];
    float*       out       = (float*)d_out;

    float *qkv;
    bf16 *hidh, *hidl, *wqTh, *wqTl, *woTh, *woTl, *oh, *ol;
    cudaGetSymbolAddress((void**)&qkv,  g_qkv);
    cudaGetSymbolAddress((void**)&hidh, g_hidh);
    cudaGetSymbolAddress((void**)&hidl, g_hidl);
    cudaGetSymbolAddress((void**)&wqTh, g_wqTh);
    cudaGetSymbolAddress((void**)&wqTl, g_wqTl);
    cudaGetSymbolAddress((void**)&woTh, g_woTh);
    cudaGetSymbolAddress((void**)&woTl, g_woTl);
    cudaGetSymbolAddress((void**)&oh,   g_oh);
    cudaGetSymbolAddress((void**)&ol,   g_ol);

    cudaFuncSetAttribute(gemm_split_kernel,
                         cudaFuncAttributeMaxDynamicSharedMemorySize, GEMM_SMEM);
    cudaFuncSetAttribute(flash4_kernel,
                         cudaFuncAttributeMaxDynamicSharedMemorySize, FLASH_SMEM);

    // 1) RoPE tables + operand conversions
    build_tables_kernel<<<(SS * HALF + 255) / 256, 256>>>(positions);
    cvt_split_kernel<<<(unsigned)(((size_t)MM * HH + 255) / 256), 256>>>(
        hidden, hidh, hidl, (size_t)MM * HH);
    {
        dim3 grid(CQKV / 32, HH / 32); dim3 blk(32, 8);
        transpose_cvt_kernel<<<grid, blk>>>(w_qkv, HH, CQKV, wqTh, wqTl);
    }
    {
        dim3 grid(HH / 32, HH / 32); dim3 blk(32, 8);
        transpose_cvt_kernel<<<grid, blk>>>(w_o, HH, HH, woTh, woTl);
    }

    // 2) QKV GEMM
    {
        dim3 grid(CQKV / 128, MM / 128);
        gemm_split_kernel<<<grid, 256, GEMM_SMEM>>>(MM, CQKV, HH,
                                                    hidh, hidl, wqTh, wqTl, qkv);
    }

    // 3) RoPE + scatter (q,k) and V transpose
    rope_scatter_kernel<<<MM, 256>>>();
    {
        dim3 grid(SS / 32, DD / 32, BB * NKVH); dim3 blk(32, 8);
        v_transpose_kernel<<<grid, blk>>>();
    }

    // 4) Flash attention
    {
        dim3 grid(SS / 128, NHD, BB);
        flash4_kernel<<<grid, 256, FLASH_SMEM>>>();
    }

    // 5) Output projection
    {
        dim3 grid(HH / 128, MM / 128);
        gemm_split_kernel<<<grid, 256, GEMM_SMEM>>>(MM, HH, HH,
                                                    oh, ol, woTh, woTl, out);
    }
}

// round 10
// speedup vs baseline: 6.1788x; 1.1072x over previous
#include <cuda_runtime.h>
#include <cuda_bf16.h>
#include <cuda_fp16.h>
#include <math.h>
#include <stdint.h>

#define BB   2
#define SS   2048
#define HH   4096
#define NHD  32
#define NKVH 8
#define DD   128
#define CQKV 6144
#define MM   (BB*SS)         // 4096
#define HALF 64
#define SCALE 0.08838834764831843f

typedef __nv_bfloat16 bf16;

// ---------------- device scratch (allocation-free) ----------------
__device__ float g_qkv [(size_t)MM*CQKV];
__device__ bf16  g_hidh[(size_t)MM*HH],    g_hidl[(size_t)MM*HH];
__device__ bf16  g_wqTh[(size_t)CQKV*HH],  g_wqTl[(size_t)CQKV*HH];
__device__ bf16  g_woTh[(size_t)HH*HH],    g_woTl[(size_t)HH*HH];
__device__ __half g_qf[(size_t)BB*NHD*SS*DD];    // fp16 Q (scaled)
__device__ __half g_kf[(size_t)BB*NKVH*SS*DD];   // fp16 K
__device__ __half g_vf[(size_t)BB*NKVH*DD*SS];   // fp16 V^T [b,kh,d,s]
__device__ bf16  g_oh[(size_t)MM*HH],      g_ol[(size_t)MM*HH];
__device__ float g_cos[SS*HALF], g_sin[SS*HALF];

// ---------------- helpers ----------------
__device__ __forceinline__ void cpa16(unsigned d, const void* s) {
    asm volatile("cp.async.ca.shared.global [%0], [%1], 16;" :: "r"(d), "l"(s));
}
__device__ __forceinline__ void cpa_commit() {
    asm volatile("cp.async.commit_group;");
}
template<int N>
__device__ __forceinline__ void cpa_wait() {
    asm volatile("cp.async.wait_group %0;" :: "n"(N));
}
__device__ __forceinline__ void mma16(float* c, const unsigned* a, const unsigned* b) {
    asm volatile(
        "mma.sync.aligned.m16n8k16.row.col.f32.bf16.bf16.f32 "
        "{%0,%1,%2,%3}, {%4,%5,%6,%7}, {%8,%9}, {%0,%1,%2,%3};"
        : "+f"(c[0]), "+f"(c[1]), "+f"(c[2]), "+f"(c[3])
        : "r"(a[0]), "r"(a[1]), "r"(a[2]), "r"(a[3]), "r"(b[0]), "r"(b[1]));
}
__device__ __forceinline__ void mma16f(float* c, const unsigned* a, const unsigned* b) {
    asm volatile(
        "mma.sync.aligned.m16n8k16.row.col.f32.f16.f16.f32 "
        "{%0,%1,%2,%3}, {%4,%5,%6,%7}, {%8,%9}, {%0,%1,%2,%3};"
        : "+f"(c[0]), "+f"(c[1]), "+f"(c[2]), "+f"(c[3])
        : "r"(a[0]), "r"(a[1]), "r"(a[2]), "r"(a[3]), "r"(b[0]), "r"(b[1]));
}
__device__ __forceinline__ void ldm4(unsigned* r, unsigned addr) {
    asm volatile("ldmatrix.sync.aligned.m8n8.x4.shared.b16 {%0,%1,%2,%3}, [%4];"
        : "=r"(r[0]), "=r"(r[1]), "=r"(r[2]), "=r"(r[3]) : "r"(addr));
}
__device__ __forceinline__ void split_pack(float x, float y, unsigned& hp, unsigned& lp) {
    bf16 xh = __float2bfloat16(x), yh = __float2bfloat16(y);
    hp = ((unsigned)__bfloat16_as_ushort(yh) << 16) | (unsigned)__bfloat16_as_ushort(xh);
    bf16 xl = __float2bfloat16(x - __bfloat162float(xh));
    bf16 yl = __float2bfloat16(y - __bfloat162float(yh));
    lp = ((unsigned)__bfloat16_as_ushort(yl) << 16) | (unsigned)__bfloat16_as_ushort(xl);
}
__device__ __forceinline__ unsigned pack_h2(float x, float y) {
    __half hx = __float2half_rn(x), hy = __float2half_rn(y);
    return ((unsigned)__half_as_ushort(hy) << 16) | (unsigned)__half_as_ushort(hx);
}

// ---------------- RoPE tables ----------------
__global__ void build_tables_kernel(const int* __restrict__ positions) {
    int idx = blockIdx.x * blockDim.x + threadIdx.x;
    if (idx >= SS * HALF) return;
    int s = idx >> 6, i = idx & 63;
    double inv = pow(10000.0, -((double)(2 * i)) / (double)DD);
    double ang = (double)positions[s] * inv;
    g_cos[idx] = (float)cos(ang);
    g_sin[idx] = (float)sin(ang);
}

// ---------------- elementwise fp32 -> bf16 hi/lo ----------------
__global__ void cvt_split_kernel(const float* __restrict__ src, bf16* __restrict__ dh,
                                 bf16* __restrict__ dl, size_t n) {
    size_t i = (size_t)blockIdx.x * blockDim.x + threadIdx.x;
    if (i >= n) return;
    float x = src[i];
    bf16 h = __float2bfloat16(x);
    dh[i] = h;
    dl[i] = __float2bfloat16(x - __bfloat162float(h));
}

// ---------------- transpose + split ----------------
__global__ void transpose_cvt_kernel(const float* __restrict__ src, int R, int C,
                                     bf16* __restrict__ dh, bf16* __restrict__ dl) {
    __shared__ float t[32][33];
    int c0 = blockIdx.x * 32, r0 = blockIdx.y * 32;
    for (int i = threadIdx.y; i < 32; i += 8)
        t[i][threadIdx.x] = src[(size_t)(r0 + i) * C + c0 + threadIdx.x];
    __syncthreads();
    for (int i = threadIdx.y; i < 32; i += 8) {
        float x = t[threadIdx.x][i];
        bf16 h = __float2bfloat16(x);
        size_t o = (size_t)(c0 + i) * R + r0 + threadIdx.x;
        dh[o] = h;
        dl[o] = __float2bfloat16(x - __bfloat162float(h));
    }
}

// ---------------- V transpose -> fp16 [b,kh,d,s] ----------------
__global__ void v_transpose_kernel() {
    __shared__ float t[32][33];
    int s0 = blockIdx.x * 32, d0 = blockIdx.y * 32;
    int bk = blockIdx.z;
    int b = bk / NKVH, kh = bk % NKVH;
    const float* src = g_qkv + (size_t)(b * SS) * CQKV + (NHD * DD + NKVH * DD) + kh * DD;
    for (int i = threadIdx.y; i < 32; i += 8)
        t[i][threadIdx.x] = src[(size_t)(s0 + i) * CQKV + d0 + threadIdx.x];
    __syncthreads();
    __half* dv = g_vf + (size_t)bk * DD * SS;
    for (int i = threadIdx.y; i < 32; i += 8)
        dv[(size_t)(d0 + i) * SS + s0 + threadIdx.x] = __float2half_rn(t[threadIdx.x][i]);
}

// ---------------- RoPE + scatter (q,k) -> fp16 ----------------
__global__ void rope_scatter_kernel() {
    const int m = blockIdx.x;
    const int b = m / SS, s = m % SS;
    const float* row = g_qkv + (size_t)m * CQKV;
    const float* ct = g_cos + s * HALF;
    const float* st = g_sin + s * HALF;

    for (int idx = threadIdx.x; idx < NHD * HALF; idx += blockDim.x) {
        int h = idx >> 6, i = idx & 63;
        float x1 = row[h * DD + i], x2 = row[h * DD + i + HALF];
        float c = ct[i], sn = st[i];
        size_t base = ((size_t)(b * NHD + h) * SS + s) * DD;
        g_qf[base + i]        = __float2half_rn((x1 * c - x2 * sn) * SCALE);
        g_qf[base + i + HALF] = __float2half_rn((x2 * c + x1 * sn) * SCALE);
    }
    for (int idx = threadIdx.x; idx < NKVH * HALF; idx += blockDim.x) {
        int h = idx >> 6, i = idx & 63;
        float x1 = row[NHD * DD + h * DD + i], x2 = row[NHD * DD + h * DD + i + HALF];
        float c = ct[i], sn = st[i];
        size_t base = ((size_t)(b * NKVH + h) * SS + s) * DD;
        g_kf[base + i]        = __float2half_rn(x1 * c - x2 * sn);
        g_kf[base + i + HALF] = __float2half_rn(x2 * c + x1 * sn);
    }
}

// ---------------- split-bf16 GEMM (HMMA + ldmatrix + L2 swizzle) ----------------
#define PW 20            // smem words per row (32 halfs = 16 words + 4 pad)
#define TW (128*PW)
#define GEMM_SMEM (8*TW*4)

__global__ __launch_bounds__(256, 1)
void gemm_split_kernel(int M, int N, int K,
                       const bf16* __restrict__ Ah, const bf16* __restrict__ Al,
                       const bf16* __restrict__ Bh, const bf16* __restrict__ Bl,
                       float* __restrict__ C) {
    extern __shared__ unsigned sw[];
    const unsigned smemBase = (unsigned)__cvta_generic_to_shared(sw);

    const int tid = threadIdx.x;
    const int wid = tid >> 5, lane = tid & 31;
    const int g = lane >> 2, tg = lane & 3;
    const int wm = wid >> 2, wn = wid & 3;

    // L2-friendly block swizzle: 16-row panels traversed column-by-column
    const int nT = N / 128;
    const int flat = blockIdx.y * gridDim.x + blockIdx.x;
    const int PH = 16;
    const int per = PH * nT;
    const int strip = flat / per;
    const int rem = flat - strip * per;
    const int colT = rem / PH;
    const int rowT = strip * PH + (rem - colT * PH);
    const size_t brow = (size_t)rowT * 128;
    const size_t bcol = (size_t)colT * 128;

    const int lr = tid >> 1, lh = tid & 1;
    const bf16* sAh = Ah + (brow + lr) * (size_t)K + lh * 16;
    const bf16* sAl = Al + (brow + lr) * (size_t)K + lh * 16;
    const bf16* sBh = Bh + (bcol + lr) * (size_t)K + lh * 16;
    const bf16* sBl = Bl + (bcol + lr) * (size_t)K + lh * 16;
    const unsigned soff = (lr * PW + lh * 8) * 4;

    const unsigned aoff = ((wm * 64 + (lane & 15)) * PW + ((lane & 16) ? 4 : 0)) * 4;
    const unsigned boff = ((wn * 32 + ((lane & 16) >> 1) + (lane & 7)) * PW
                           + ((lane & 8) ? 4 : 0)) * 4;

#define GISSUE(st, k0) {                                                     \
        unsigned a0 = smemBase + ((st) * TW) * 4 + soff;                     \
        cpa16(a0, sAh + (k0)); cpa16(a0 + 16, sAh + (k0) + 8);               \
        unsigned a1 = smemBase + ((2 + (st)) * TW) * 4 + soff;               \
        cpa16(a1, sAl + (k0)); cpa16(a1 + 16, sAl + (k0) + 8);               \
        unsigned a2 = smemBase + ((4 + (st)) * TW) * 4 + soff;               \
        cpa16(a2, sBh + (k0)); cpa16(a2 + 16, sBh + (k0) + 8);               \
        unsigned a3 = smemBase + ((6 + (st)) * TW) * 4 + soff;               \
        cpa16(a3, sBl + (k0)); cpa16(a3 + 16, sBl + (k0) + 8);               \
    }

    float acc[4][4][4];
#pragma unroll
    for (int mt = 0; mt < 4; mt++)
#pragma unroll
        for (int nt = 0; nt < 4; nt++)
#pragma unroll
            for (int i = 0; i < 4; i++) acc[mt][nt][i] = 0.f;

    const int nIter = K / 32;
    GISSUE(0, 0); cpa_commit();

    for (int it = 0; it < nIter; it++) {
        if (it + 1 < nIter) { GISSUE((it + 1) & 1, (it + 1) * 32); cpa_commit(); cpa_wait<1>(); }
        else                { cpa_wait<0>(); }
        __syncthreads();

        const int st = it & 1;
        const unsigned aHB = smemBase + (st * TW) * 4;
        const unsigned aLB = smemBase + ((2 + st) * TW) * 4;
        const unsigned bHB = smemBase + ((4 + st) * TW) * 4;
        const unsigned bLB = smemBase + ((6 + st) * TW) * 4;

#pragma unroll
        for (int ks = 0; ks < 2; ks++) {
            const unsigned kb = ks * 32;
            unsigned ah[4][4], al[4][4], bh[2][4], bl[2][4];
#pragma unroll
            for (int p = 0; p < 2; p++) {
                ldm4(bh[p], bHB + boff + p * 16 * PW * 4 + kb);
                ldm4(bl[p], bLB + boff + p * 16 * PW * 4 + kb);
            }
#pragma unroll
            for (int mt = 0; mt < 4; mt++) {
                ldm4(ah[mt], aHB + aoff + mt * 16 * PW * 4 + kb);
                ldm4(al[mt], aLB + aoff + mt * 16 * PW * 4 + kb);
            }
#pragma unroll
            for (int mt = 0; mt < 4; mt++)
#pragma unroll
                for (int nt = 0; nt < 4; nt++)
                    mma16(acc[mt][nt], ah[mt], &bh[nt >> 1][(nt & 1) * 2]);
#pragma unroll
            for (int mt = 0; mt < 4; mt++)
#pragma unroll
                for (int nt = 0; nt < 4; nt++)
                    mma16(acc[mt][nt], ah[mt], &bl[nt >> 1][(nt & 1) * 2]);
#pragma unroll
            for (int mt = 0; mt < 4; mt++)
#pragma unroll
                for (int nt = 0; nt < 4; nt++)
                    mma16(acc[mt][nt], al[mt], &bh[nt >> 1][(nt & 1) * 2]);
        }
        __syncthreads();
    }

#pragma unroll
    for (int mt = 0; mt < 4; mt++)
#pragma unroll
        for (int nt = 0; nt < 4; nt++) {
            size_t row = brow + wm * 64 + mt * 16 + g;
            size_t col = bcol + wn * 32 + nt * 8 + 2 * tg;
            *(float2*)(C + row * N + col) = make_float2(acc[mt][nt][0], acc[mt][nt][1]);
            *(float2*)(C + (row + 8) * N + col) = make_float2(acc[mt][nt][2], acc[mt][nt][3]);
        }
#undef GISSUE
}

// ---------------- Flash attention: single-pass fp16, 256 thr, 128 q rows ----
#define KQP 68   // Q/K row pitch in words (128 halfs + pad)
#define VP  36   // V row pitch in words (64 halfs + pad)
#define F_QH 0
#define F_KH(st) (8704 + (st)*4352)
#define F_VH(st) (17408 + (st)*4608)
#define FLASH_SMEM (26624*4)

__global__ __launch_bounds__(256, 1)
void flash5_kernel() {
    extern __shared__ unsigned sw[];
    const unsigned smemBase = (unsigned)__cvta_generic_to_shared(sw);

    const int bx = blockIdx.x, h = blockIdx.y, b = blockIdx.z;
    const int tid = threadIdx.x, wid = tid >> 5, lane = tid & 31;
    const int g = lane >> 2, tg = lane & 3;
    const int qbase = bx * 128;
    const int kh = h >> 2;

    const int qr = tid >> 1, qh2 = tid & 1;
    const int krow = tid >> 2, kq = tid & 3;
    const int vrow = tid >> 1, vh2 = tid & 1;

    const size_t qg0 = ((size_t)(b * NHD + h) * SS + qbase + qr) * DD + qh2 * 64;
    const size_t krowB = (size_t)(b * NKVH + kh) * SS;
    const size_t vg0 = ((size_t)(b * NKVH + kh) * DD + vrow) * SS + vh2 * 32;

    // stage Q (once)
    {
        const __half* sQ = g_qf + qg0;
        unsigned dq = smemBase + (F_QH + qr * KQP + qh2 * 32) * 4;
#pragma unroll
        for (int j = 0; j < 8; j++) cpa16(dq + j * 16, sQ + j * 8);
    }
#define FKV(t, st) {                                                          \
        const __half* sK = g_kf + (krowB + (t) * 64 + krow) * DD + kq * 32;   \
        unsigned dk = smemBase + (F_KH(st) + krow * KQP + kq * 16) * 4;       \
        _Pragma("unroll")                                                     \
        for (int j = 0; j < 4; j++) cpa16(dk + j * 16, sK + j * 8);           \
        const __half* sV = g_vf + vg0 + (t) * 64;                             \
        unsigned dv = smemBase + (F_VH(st) + vrow * VP + vh2 * 16) * 4;       \
        _Pragma("unroll")                                                     \
        for (int j = 0; j < 4; j++) cpa16(dv + j * 16, sV + j * 8);           \
    }

    FKV(0, 0); cpa_commit();

    float Oacc[16][4];
#pragma unroll
    for (int nt = 0; nt < 16; nt++)
#pragma unroll
        for (int i = 0; i < 4; i++) Oacc[nt][i] = 0.f;
    float m0 = -1e30f, m1 = -1e30f, l0 = 0.f, l1 = 0.f;

    const unsigned aoffQ = ((wid * 16 + (lane & 15)) * KQP + ((lane & 16) ? 4 : 0)) * 4;
    const unsigned boffK = ((((lane & 16) >> 1) + (lane & 7)) * KQP + ((lane & 8) ? 4 : 0)) * 4;
    const unsigned boffV = ((((lane & 16) >> 1) + (lane & 7)) * VP + ((lane & 8) ? 4 : 0)) * 4;
    const unsigned qHB = smemBase + F_QH * 4;

    const int ntile = 2 * bx + 2;
    int st = 0;
    for (int t = 0; t < ntile; t++) {
        if (t + 1 < ntile) { FKV(t + 1, st ^ 1); cpa_commit(); cpa_wait<1>(); }
        else               { cpa_wait<0>(); }
        __syncthreads();

        const unsigned kHB = smemBase + F_KH(st) * 4;
        const unsigned vHB = smemBase + F_VH(st) * 4;

        // ---- scores: S(16x64 per warp) = Q @ K^T, single-pass fp16
        float sacc[8][4];
#pragma unroll
        for (int nt = 0; nt < 8; nt++)
#pragma unroll
            for (int i = 0; i < 4; i++) sacc[nt][i] = 0.f;

#pragma unroll
        for (int ks = 0; ks < 8; ks++) {
            const unsigned kb = ks * 32;
            unsigned ah[4], bh[4][4];
            ldm4(ah, qHB + aoffQ + kb);
#pragma unroll
            for (int p = 0; p < 4; p++)
                ldm4(bh[p], kHB + boffK + p * 16 * KQP * 4 + kb);
#pragma unroll
            for (int nt = 0; nt < 8; nt++)
                mma16f(sacc[nt], ah, &bh[nt >> 1][(nt & 1) * 2]);
        }

        // ---- causal mask (tiles overlapping the diagonal)
        if (t >= 2 * bx) {
            int r0 = qbase + wid * 16 + g, r1 = r0 + 8;
#pragma unroll
            for (int nt = 0; nt < 8; nt++) {
                int c0 = t * 64 + nt * 8 + 2 * tg, c1 = c0 + 1;
                if (c0 > r0) sacc[nt][0] = -1e30f;
                if (c1 > r0) sacc[nt][1] = -1e30f;
                if (c0 > r1) sacc[nt][2] = -1e30f;
                if (c1 > r1) sacc[nt][3] = -1e30f;
            }
        }

        // ---- online softmax
        float tm0 = -1e30f, tm1 = -1e30f;
#pragma unroll
        for (int nt = 0; nt < 8; nt++) {
            tm0 = fmaxf(tm0, fmaxf(sacc[nt][0], sacc[nt][1]));
            tm1 = fmaxf(tm1, fmaxf(sacc[nt][2], sacc[nt][3]));
        }
        tm0 = fmaxf(tm0, __shfl_xor_sync(0xffffffffu, tm0, 1));
        tm0 = fmaxf(tm0, __shfl_xor_sync(0xffffffffu, tm0, 2));
        tm1 = fmaxf(tm1, __shfl_xor_sync(0xffffffffu, tm1, 1));
        tm1 = fmaxf(tm1, __shfl_xor_sync(0xffffffffu, tm1, 2));

        float mn0 = fmaxf(m0, tm0), mn1 = fmaxf(m1, tm1);
        float a0 = __expf(m0 - mn0), a1 = __expf(m1 - mn1);
        l0 *= a0; l1 *= a1;
#pragma unroll
        for (int nt = 0; nt < 16; nt++) {
            Oacc[nt][0] *= a0; Oacc[nt][1] *= a0;
            Oacc[nt][2] *= a1; Oacc[nt][3] *= a1;
        }

        float p0a[8], p1a[8], p2a[8], p3a[8];
        float rs0 = 0.f, rs1 = 0.f;
#pragma unroll
        for (int nt = 0; nt < 8; nt++) {
            p0a[nt] = __expf(sacc[nt][0] - mn0);
            p1a[nt] = __expf(sacc[nt][1] - mn0);
            p2a[nt] = __expf(sacc[nt][2] - mn1);
            p3a[nt] = __expf(sacc[nt][3] - mn1);
            rs0 += p0a[nt] + p1a[nt];
            rs1 += p2a[nt] + p3a[nt];
        }
        rs0 += __shfl_xor_sync(0xffffffffu, rs0, 1);
        rs0 += __shfl_xor_sync(0xffffffffu, rs0, 2);
        rs1 += __shfl_xor_sync(0xffffffffu, rs1, 1);
        rs1 += __shfl_xor_sync(0xffffffffu, rs1, 2);
        l0 += rs0; l1 += rs1;
        m0 = mn0; m1 = mn1;

        // ---- PV: O(16x128 per warp) += P(16x64) @ V, single-pass fp16
#pragma unroll
        for (int ks = 0; ks < 4; ks++) {
            const unsigned kb = ks * 32;
            unsigned aH[4];
            aH[0] = pack_h2(p0a[2 * ks],     p1a[2 * ks]);
            aH[1] = pack_h2(p2a[2 * ks],     p3a[2 * ks]);
            aH[2] = pack_h2(p0a[2 * ks + 1], p1a[2 * ks + 1]);
            aH[3] = pack_h2(p2a[2 * ks + 1], p3a[2 * ks + 1]);
#pragma unroll
            for (int p = 0; p < 8; p++) {
                unsigned vbh[4];
                ldm4(vbh, vHB + boffV + p * 16 * VP * 4 + kb);
                mma16f(Oacc[2 * p],     aH, &vbh[0]);
                mma16f(Oacc[2 * p + 1], aH, &vbh[2]);
            }
        }
        __syncthreads();
        st ^= 1;
    }

    // ---- epilogue: O hi/lo bf16 (feeds 3-pass O-proj GEMM)
    float inv0 = 1.f / l0, inv1 = 1.f / l1;
    int r0 = qbase + wid * 16 + g;
    size_t ro0 = ((size_t)(b * SS) + r0) * (NHD * DD) + h * DD;
    size_t ro1 = ((size_t)(b * SS) + r0 + 8) * (NHD * DD) + h * DD;
#pragma unroll
    for (int nt = 0; nt < 16; nt++) {
        int c = nt * 8 + 2 * tg;
        float o0 = Oacc[nt][0] * inv0, o1 = Oacc[nt][1] * inv0;
        float o2 = Oacc[nt][2] * inv1, o3 = Oacc[nt][3] * inv1;
        unsigned hp, lp;
        split_pack(o0, o1, hp, lp);
        *(unsigned*)(g_oh + ro0 + c) = hp;
        *(unsigned*)(g_ol + ro0 + c) = lp;
        split_pack(o2, o3, hp, lp);
        *(unsigned*)(g_oh + ro1 + c) = hp;
        *(unsigned*)(g_ol + ro1 + c) = lp;
    }
#undef FKV
}

// ---------------- launch ----------------
extern "C" void kernel_launch(void* const* d_in, const int* in_sizes, int n_in,
                              void* d_out, int out_size) {
    const int*   positions = (const int*)d_in[0];
    const float* hidden    = (const float*)d_in[1];
    const float* w_qkv     = (const float*)d_in[2];
    const float* w_o       = (const float*)d_in[3];
    float*       out       = (float*)d_out;

    float *qkv;
    bf16 *hidh, *hidl, *wqTh, *wqTl, *woTh, *woTl, *oh, *ol;
    cudaGetSymbolAddress((void**)&qkv,  g_qkv);
    cudaGetSymbolAddress((void**)&hidh, g_hidh);
    cudaGetSymbolAddress((void**)&hidl, g_hidl);
    cudaGetSymbolAddress((void**)&wqTh, g_wqTh);
    cudaGetSymbolAddress((void**)&wqTl, g_wqTl);
    cudaGetSymbolAddress((void**)&woTh, g_woTh);
    cudaGetSymbolAddress((void**)&woTl, g_woTl);
    cudaGetSymbolAddress((void**)&oh,   g_oh);
    cudaGetSymbolAddress((void**)&ol,   g_ol);

    cudaFuncSetAttribute(gemm_split_kernel,
                         cudaFuncAttributeMaxDynamicSharedMemorySize, GEMM_SMEM);
    cudaFuncSetAttribute(flash5_kernel,
                         cudaFuncAttributeMaxDynamicSharedMemorySize, FLASH_SMEM);

    // 1) RoPE tables + operand conversions
    build_tables_kernel<<<(SS * HALF + 255) / 256, 256>>>(positions);
    cvt_split_kernel<<<(unsigned)(((size_t)MM * HH + 255) / 256), 256>>>(
        hidden, hidh, hidl, (size_t)MM * HH);
    {
        dim3 grid(CQKV / 32, HH / 32); dim3 blk(32, 8);
        transpose_cvt_kernel<<<grid, blk>>>(w_qkv, HH, CQKV, wqTh, wqTl);
    }
    {
        dim3 grid(HH / 32, HH / 32); dim3 blk(32, 8);
        transpose_cvt_kernel<<<grid, blk>>>(w_o, HH, HH, woTh, woTl);
    }

    // 2) QKV GEMM
    {
        dim3 grid(CQKV / 128, MM / 128);
        gemm_split_kernel<<<grid, 256, GEMM_SMEM>>>(MM, CQKV, HH,
                                                    hidh, hidl, wqTh, wqTl, qkv);
    }

    // 3) RoPE + scatter (q,k) and V transpose
    rope_scatter_kernel<<<MM, 256>>>();
    {
        dim3 grid(SS / 32, DD / 32, BB * NKVH); dim3 blk(32, 8);
        v_transpose_kernel<<<grid, blk>>>();
    }

    // 4) Flash attention (fp16 single-pass)
    {
        dim3 grid(SS / 128, NHD, BB);
        flash5_kernel<<<grid, 256, FLASH_SMEM>>>();
    }

    // 5) Output projection
    {
        dim3 grid(HH / 128, MM / 128);
        gemm_split_kernel<<<grid, 256, GEMM_SMEM>>>(MM, HH, HH,
                                                    oh, ol, woTh, woTl, out);
    }
}

// round 12
// speedup vs baseline: 8.0302x; 1.2996x over previous
#include <cuda_runtime.h>
#include <cuda_bf16.h>
#include <cuda_fp16.h>
#include <math.h>
#include <stdint.h>

#define BB   2
#define SS   2048
#define HH   4096
#define NHD  32
#define NKVH 8
#define DD   128
#define CQKV 6144
#define MM   (BB*SS)         // 4096
#define HALF 64
#define SCALE 0.08838834764831843f

// ---------------- device scratch (allocation-free) ----------------
__device__ float  g_qkv [(size_t)MM*CQKV];
__device__ __half g_hidh[(size_t)MM*HH],   g_hidl[(size_t)MM*HH];   // A hi/lo (QKV gemm)
__device__ __half g_wqTh[(size_t)CQKV*HH];                          // B (QKV gemm), single fp16
__device__ __half g_woTh[(size_t)HH*HH];                            // B (O-proj), single fp16
__device__ __half g_qf[(size_t)BB*NHD*SS*DD];    // fp16 Q (scaled)
__device__ __half g_kf[(size_t)BB*NKVH*SS*DD];   // fp16 K
__device__ __half g_vf[(size_t)BB*NKVH*DD*SS];   // fp16 V^T [b,kh,d,s]
__device__ __half g_oh[(size_t)MM*HH],     g_ol[(size_t)MM*HH];     // A hi/lo (O-proj)
__device__ float  g_cos[SS*HALF], g_sin[SS*HALF];

// ---------------- helpers ----------------
__device__ __forceinline__ void cpa16(unsigned d, const void* s) {
    asm volatile("cp.async.ca.shared.global [%0], [%1], 16;" :: "r"(d), "l"(s));
}
__device__ __forceinline__ void cpa_commit() {
    asm volatile("cp.async.commit_group;");
}
template<int N>
__device__ __forceinline__ void cpa_wait() {
    asm volatile("cp.async.wait_group %0;" :: "n"(N));
}
__device__ __forceinline__ void mma16f(float* c, const unsigned* a, const unsigned* b) {
    asm volatile(
        "mma.sync.aligned.m16n8k16.row.col.f32.f16.f16.f32 "
        "{%0,%1,%2,%3}, {%4,%5,%6,%7}, {%8,%9}, {%0,%1,%2,%3};"
        : "+f"(c[0]), "+f"(c[1]), "+f"(c[2]), "+f"(c[3])
        : "r"(a[0]), "r"(a[1]), "r"(a[2]), "r"(a[3]), "r"(b[0]), "r"(b[1]));
}
__device__ __forceinline__ void ldm4(unsigned* r, unsigned addr) {
    asm volatile("ldmatrix.sync.aligned.m8n8.x4.shared.b16 {%0,%1,%2,%3}, [%4];"
        : "=r"(r[0]), "=r"(r[1]), "=r"(r[2]), "=r"(r[3]) : "r"(addr));
}
__device__ __forceinline__ unsigned pack_h2(float x, float y) {
    __half hx = __float2half_rn(x), hy = __float2half_rn(y);
    return ((unsigned)__half_as_ushort(hy) << 16) | (unsigned)__half_as_ushort(hx);
}
// fp16 hi/lo split-pack of two floats
__device__ __forceinline__ void split_pack_h(float x, float y, unsigned& hp, unsigned& lp) {
    __half xh = __float2half_rn(x), yh = __float2half_rn(y);
    hp = ((unsigned)__half_as_ushort(yh) << 16) | (unsigned)__half_as_ushort(xh);
    __half xl = __float2half_rn(x - __half2float(xh));
    __half yl = __float2half_rn(y - __half2float(yh));
    lp = ((unsigned)__half_as_ushort(yl) << 16) | (unsigned)__half_as_ushort(xl);
}

// ---------------- RoPE tables ----------------
__global__ void build_tables_kernel(const int* __restrict__ positions) {
    int idx = blockIdx.x * blockDim.x + threadIdx.x;
    if (idx >= SS * HALF) return;
    int s = idx >> 6, i = idx & 63;
    double inv = pow(10000.0, -((double)(2 * i)) / (double)DD);
    double ang = (double)positions[s] * inv;
    g_cos[idx] = (float)cos(ang);
    g_sin[idx] = (float)sin(ang);
}

// ---------------- elementwise fp32 -> fp16 hi/lo ----------------
__global__ void cvt_split_kernel(const float* __restrict__ src, __half* __restrict__ dh,
                                 __half* __restrict__ dl, size_t n) {
    size_t i = (size_t)blockIdx.x * blockDim.x + threadIdx.x;
    if (i >= n) return;
    float x = src[i];
    __half h = __float2half_rn(x);
    dh[i] = h;
    dl[i] = __float2half_rn(x - __half2float(h));
}

// ---------------- transpose + cvt: src [R][C] f32 -> dst [C][R] fp16 ----------------
__global__ void transpose_cvt_kernel(const float* __restrict__ src, int R, int C,
                                     __half* __restrict__ dh) {
    __shared__ float t[32][33];
    int c0 = blockIdx.x * 32, r0 = blockIdx.y * 32;
    for (int i = threadIdx.y; i < 32; i += 8)
        t[i][threadIdx.x] = src[(size_t)(r0 + i) * C + c0 + threadIdx.x];
    __syncthreads();
    for (int i = threadIdx.y; i < 32; i += 8)
        dh[(size_t)(c0 + i) * R + r0 + threadIdx.x] = __float2half_rn(t[threadIdx.x][i]);
}

// ---------------- V transpose -> fp16 [b,kh,d,s] ----------------
__global__ void v_transpose_kernel() {
    __shared__ float t[32][33];
    int s0 = blockIdx.x * 32, d0 = blockIdx.y * 32;
    int bk = blockIdx.z;
    int b = bk / NKVH, kh = bk % NKVH;
    const float* src = g_qkv + (size_t)(b * SS) * CQKV + (NHD * DD + NKVH * DD) + kh * DD;
    for (int i = threadIdx.y; i < 32; i += 8)
        t[i][threadIdx.x] = src[(size_t)(s0 + i) * CQKV + d0 + threadIdx.x];
    __syncthreads();
    __half* dv = g_vf + (size_t)bk * DD * SS;
    for (int i = threadIdx.y; i < 32; i += 8)
        dv[(size_t)(d0 + i) * SS + s0 + threadIdx.x] = __float2half_rn(t[threadIdx.x][i]);
}

// ---------------- RoPE + scatter (q,k) -> fp16 ----------------
__global__ void rope_scatter_kernel() {
    const int m = blockIdx.x;
    const int b = m / SS, s = m % SS;
    const float* row = g_qkv + (size_t)m * CQKV;
    const float* ct = g_cos + s * HALF;
    const float* st = g_sin + s * HALF;

    for (int idx = threadIdx.x; idx < NHD * HALF; idx += blockDim.x) {
        int h = idx >> 6, i = idx & 63;
        float x1 = row[h * DD + i], x2 = row[h * DD + i + HALF];
        float c = ct[i], sn = st[i];
        size_t base = ((size_t)(b * NHD + h) * SS + s) * DD;
        g_qf[base + i]        = __float2half_rn((x1 * c - x2 * sn) * SCALE);
        g_qf[base + i + HALF] = __float2half_rn((x2 * c + x1 * sn) * SCALE);
    }
    for (int idx = threadIdx.x; idx < NKVH * HALF; idx += blockDim.x) {
        int h = idx >> 6, i = idx & 63;
        float x1 = row[NHD * DD + h * DD + i], x2 = row[NHD * DD + h * DD + i + HALF];
        float c = ct[i], sn = st[i];
        size_t base = ((size_t)(b * NKVH + h) * SS + s) * DD;
        g_kf[base + i]        = __float2half_rn(x1 * c - x2 * sn);
        g_kf[base + i + HALF] = __float2half_rn(x2 * c + x1 * sn);
    }
}

// ---------------- 2-pass split-A fp16 GEMM (HMMA + ldmatrix + L2 swizzle) ----
// C[M][N] = sum_k (Ah+Al)[m][k] * Bh[n][k].  B rounded once to fp16.
// 128x128x32 tiles, 2-stage cp.async, 256 thr (8 warps 2x4, warp tile 64x32).
#define PW 20            // smem words per row (32 halfs = 16 words + 4 pad)
#define TW (128*PW)
#define GEMM_SMEM (6*TW*4)

__global__ __launch_bounds__(256, 1)
void gemm_split_kernel(int M, int N, int K,
                       const __half* __restrict__ Ah, const __half* __restrict__ Al,
                       const __half* __restrict__ Bh,
                       float* __restrict__ C) {
    extern __shared__ unsigned sw[];
    const unsigned smemBase = (unsigned)__cvta_generic_to_shared(sw);

    const int tid = threadIdx.x;
    const int wid = tid >> 5, lane = tid & 31;
    const int g = lane >> 2, tg = lane & 3;
    const int wm = wid >> 2, wn = wid & 3;

    // L2-friendly block swizzle: 16-row panels traversed column-by-column
    const int nT = N / 128;
    const int flat = blockIdx.y * gridDim.x + blockIdx.x;
    const int PH = 16;
    const int per = PH * nT;
    const int strip = flat / per;
    const int rem = flat - strip * per;
    const int colT = rem / PH;
    const int rowT = strip * PH + (rem - colT * PH);
    const size_t brow = (size_t)rowT * 128;
    const size_t bcol = (size_t)colT * 128;

    const int lr = tid >> 1, lh = tid & 1;
    const __half* sAh = Ah + (brow + lr) * (size_t)K + lh * 16;
    const __half* sAl = Al + (brow + lr) * (size_t)K + lh * 16;
    const __half* sBh = Bh + (bcol + lr) * (size_t)K + lh * 16;
    const unsigned soff = (lr * PW + lh * 8) * 4;

    const unsigned aoff = ((wm * 64 + (lane & 15)) * PW + ((lane & 16) ? 4 : 0)) * 4;
    const unsigned boff = ((wn * 32 + ((lane & 16) >> 1) + (lane & 7)) * PW
                           + ((lane & 8) ? 4 : 0)) * 4;

#define GISSUE(st, k0) {                                                     \
        unsigned a0 = smemBase + ((st) * TW) * 4 + soff;                     \
        cpa16(a0, sAh + (k0)); cpa16(a0 + 16, sAh + (k0) + 8);               \
        unsigned a1 = smemBase + ((2 + (st)) * TW) * 4 + soff;               \
        cpa16(a1, sAl + (k0)); cpa16(a1 + 16, sAl + (k0) + 8);               \
        unsigned a2 = smemBase + ((4 + (st)) * TW) * 4 + soff;               \
        cpa16(a2, sBh + (k0)); cpa16(a2 + 16, sBh + (k0) + 8);               \
    }

    float acc[4][4][4];
#pragma unroll
    for (int mt = 0; mt < 4; mt++)
#pragma unroll
        for (int nt = 0; nt < 4; nt++)
#pragma unroll
            for (int i = 0; i < 4; i++) acc[mt][nt][i] = 0.f;

    const int nIter = K / 32;
    GISSUE(0, 0); cpa_commit();

    for (int it = 0; it < nIter; it++) {
        if (it + 1 < nIter) { GISSUE((it + 1) & 1, (it + 1) * 32); cpa_commit(); cpa_wait<1>(); }
        else                { cpa_wait<0>(); }
        __syncthreads();

        const int st = it & 1;
        const unsigned aHB = smemBase + (st * TW) * 4;
        const unsigned aLB = smemBase + ((2 + st) * TW) * 4;
        const unsigned bHB = smemBase + ((4 + st) * TW) * 4;

#pragma unroll
        for (int ks = 0; ks < 2; ks++) {
            const unsigned kb = ks * 32;
            unsigned ah[4][4], al[4][4], bh[2][4];
#pragma unroll
            for (int p = 0; p < 2; p++)
                ldm4(bh[p], bHB + boff + p * 16 * PW * 4 + kb);
#pragma unroll
            for (int mt = 0; mt < 4; mt++) {
                ldm4(ah[mt], aHB + aoff + mt * 16 * PW * 4 + kb);
                ldm4(al[mt], aLB + aoff + mt * 16 * PW * 4 + kb);
            }
#pragma unroll
            for (int mt = 0; mt < 4; mt++)
#pragma unroll
                for (int nt = 0; nt < 4; nt++)
                    mma16f(acc[mt][nt], ah[mt], &bh[nt >> 1][(nt & 1) * 2]);
#pragma unroll
            for (int mt = 0; mt < 4; mt++)
#pragma unroll
                for (int nt = 0; nt < 4; nt++)
                    mma16f(acc[mt][nt], al[mt], &bh[nt >> 1][(nt & 1) * 2]);
        }
        __syncthreads();
    }

#pragma unroll
    for (int mt = 0; mt < 4; mt++)
#pragma unroll
        for (int nt = 0; nt < 4; nt++) {
            size_t row = brow + wm * 64 + mt * 16 + g;
            size_t col = bcol + wn * 32 + nt * 8 + 2 * tg;
            *(float2*)(C + row * N + col) = make_float2(acc[mt][nt][0], acc[mt][nt][1]);
            *(float2*)(C + (row + 8) * N + col) = make_float2(acc[mt][nt][2], acc[mt][nt][3]);
        }
#undef GISSUE
}

// ---------------- Flash attention: single-pass fp16, 256 thr, 128 q rows ----
#define KQP 68   // Q/K row pitch in words (128 halfs + pad)
#define VP  36   // V row pitch in words (64 halfs + pad)
#define F_QH 0
#define F_KH(st) (8704 + (st)*4352)
#define F_VH(st) (17408 + (st)*4608)
#define FLASH_SMEM (26624*4)

__global__ __launch_bounds__(256, 1)
void flash5_kernel() {
    extern __shared__ unsigned sw[];
    const unsigned smemBase = (unsigned)__cvta_generic_to_shared(sw);

    const int bx = blockIdx.x, h = blockIdx.y, b = blockIdx.z;
    const int tid = threadIdx.x, wid = tid >> 5, lane = tid & 31;
    const int g = lane >> 2, tg = lane & 3;
    const int qbase = bx * 128;
    const int kh = h >> 2;

    const int qr = tid >> 1, qh2 = tid & 1;
    const int krow = tid >> 2, kq = tid & 3;
    const int vrow = tid >> 1, vh2 = tid & 1;

    const size_t qg0 = ((size_t)(b * NHD + h) * SS + qbase + qr) * DD + qh2 * 64;
    const size_t krowB = (size_t)(b * NKVH + kh) * SS;
    const size_t vg0 = ((size_t)(b * NKVH + kh) * DD + vrow) * SS + vh2 * 32;

    // stage Q (once)
    {
        const __half* sQ = g_qf + qg0;
        unsigned dq = smemBase + (F_QH + qr * KQP + qh2 * 32) * 4;
#pragma unroll
        for (int j = 0; j < 8; j++) cpa16(dq + j * 16, sQ + j * 8);
    }
#define FKV(t, st) {                                                          \
        const __half* sK = g_kf + (krowB + (t) * 64 + krow) * DD + kq * 32;   \
        unsigned dk = smemBase + (F_KH(st) + krow * KQP + kq * 16) * 4;       \
        _Pragma("unroll")                                                     \
        for (int j = 0; j < 4; j++) cpa16(dk + j * 16, sK + j * 8);           \
        const __half* sV = g_vf + vg0 + (t) * 64;                             \
        unsigned dv = smemBase + (F_VH(st) + vrow * VP + vh2 * 16) * 4;       \
        _Pragma("unroll")                                                     \
        for (int j = 0; j < 4; j++) cpa16(dv + j * 16, sV + j * 8);           \
    }

    FKV(0, 0); cpa_commit();

    float Oacc[16][4];
#pragma unroll
    for (int nt = 0; nt < 16; nt++)
#pragma unroll
        for (int i = 0; i < 4; i++) Oacc[nt][i] = 0.f;
    float m0 = -1e30f, m1 = -1e30f, l0 = 0.f, l1 = 0.f;

    const unsigned aoffQ = ((wid * 16 + (lane & 15)) * KQP + ((lane & 16) ? 4 : 0)) * 4;
    const unsigned boffK = ((((lane & 16) >> 1) + (lane & 7)) * KQP + ((lane & 8) ? 4 : 0)) * 4;
    const unsigned boffV = ((((lane & 16) >> 1) + (lane & 7)) * VP + ((lane & 8) ? 4 : 0)) * 4;
    const unsigned qHB = smemBase + F_QH * 4;

    const int ntile = 2 * bx + 2;
    int st = 0;
    for (int t = 0; t < ntile; t++) {
        if (t + 1 < ntile) { FKV(t + 1, st ^ 1); cpa_commit(); cpa_wait<1>(); }
        else               { cpa_wait<0>(); }
        __syncthreads();

        const unsigned kHB = smemBase + F_KH(st) * 4;
        const unsigned vHB = smemBase + F_VH(st) * 4;

        // ---- scores: S(16x64 per warp) = Q @ K^T, single-pass fp16
        float sacc[8][4];
#pragma unroll
        for (int nt = 0; nt < 8; nt++)
#pragma unroll
            for (int i = 0; i < 4; i++) sacc[nt][i] = 0.f;

#pragma unroll
        for (int ks = 0; ks < 8; ks++) {
            const unsigned kb = ks * 32;
            unsigned ah[4], bh[4][4];
            ldm4(ah, qHB + aoffQ + kb);
#pragma unroll
            for (int p = 0; p < 4; p++)
                ldm4(bh[p], kHB + boffK + p * 16 * KQP * 4 + kb);
#pragma unroll
            for (int nt = 0; nt < 8; nt++)
                mma16f(sacc[nt], ah, &bh[nt >> 1][(nt & 1) * 2]);
        }

        // ---- causal mask (tiles overlapping the diagonal)
        if (t >= 2 * bx) {
            int r0 = qbase + wid * 16 + g, r1 = r0 + 8;
#pragma unroll
            for (int nt = 0; nt < 8; nt++) {
                int c0 = t * 64 + nt * 8 + 2 * tg, c1 = c0 + 1;
                if (c0 > r0) sacc[nt][0] = -1e30f;
                if (c1 > r0) sacc[nt][1] = -1e30f;
                if (c0 > r1) sacc[nt][2] = -1e30f;
                if (c1 > r1) sacc[nt][3] = -1e30f;
            }
        }

        // ---- online softmax
        float tm0 = -1e30f, tm1 = -1e30f;
#pragma unroll
        for (int nt = 0; nt < 8; nt++) {
            tm0 = fmaxf(tm0, fmaxf(sacc[nt][0], sacc[nt][1]));
            tm1 = fmaxf(tm1, fmaxf(sacc[nt][2], sacc[nt][3]));
        }
        tm0 = fmaxf(tm0, __shfl_xor_sync(0xffffffffu, tm0, 1));
        tm0 = fmaxf(tm0, __shfl_xor_sync(0xffffffffu, tm0, 2));
        tm1 = fmaxf(tm1, __shfl_xor_sync(0xffffffffu, tm1, 1));
        tm1 = fmaxf(tm1, __shfl_xor_sync(0xffffffffu, tm1, 2));

        float mn0 = fmaxf(m0, tm0), mn1 = fmaxf(m1, tm1);
        float a0 = __expf(m0 - mn0), a1 = __expf(m1 - mn1);
        l0 *= a0; l1 *= a1;
#pragma unroll
        for (int nt = 0; nt < 16; nt++) {
            Oacc[nt][0] *= a0; Oacc[nt][1] *= a0;
            Oacc[nt][2] *= a1; Oacc[nt][3] *= a1;
        }

        float p0a[8], p1a[8], p2a[8], p3a[8];
        float rs0 = 0.f, rs1 = 0.f;
#pragma unroll
        for (int nt = 0; nt < 8; nt++) {
            p0a[nt] = __expf(sacc[nt][0] - mn0);
            p1a[nt] = __expf(sacc[nt][1] - mn0);
            p2a[nt] = __expf(sacc[nt][2] - mn1);
            p3a[nt] = __expf(sacc[nt][3] - mn1);
            rs0 += p0a[nt] + p1a[nt];
            rs1 += p2a[nt] + p3a[nt];
        }
        rs0 += __shfl_xor_sync(0xffffffffu, rs0, 1);
        rs0 += __shfl_xor_sync(0xffffffffu, rs0, 2);
        rs1 += __shfl_xor_sync(0xffffffffu, rs1, 1);
        rs1 += __shfl_xor_sync(0xffffffffu, rs1, 2);
        l0 += rs0; l1 += rs1;
        m0 = mn0; m1 = mn1;

        // ---- PV: O(16x128 per warp) += P(16x64) @ V, single-pass fp16
#pragma unroll
        for (int ks = 0; ks < 4; ks++) {
            const unsigned kb = ks * 32;
            unsigned aH[4];
            aH[0] = pack_h2(p0a[2 * ks],     p1a[2 * ks]);
            aH[1] = pack_h2(p2a[2 * ks],     p3a[2 * ks]);
            aH[2] = pack_h2(p0a[2 * ks + 1], p1a[2 * ks + 1]);
            aH[3] = pack_h2(p2a[2 * ks + 1], p3a[2 * ks + 1]);
#pragma unroll
            for (int p = 0; p < 8; p++) {
                unsigned vbh[4];
                ldm4(vbh, vHB + boffV + p * 16 * VP * 4 + kb);
                mma16f(Oacc[2 * p],     aH, &vbh[0]);
                mma16f(Oacc[2 * p + 1], aH, &vbh[2]);
            }
        }
        __syncthreads();
        st ^= 1;
    }

    // ---- epilogue: O fp16 hi/lo (feeds 2-pass O-proj GEMM)
    float inv0 = 1.f / l0, inv1 = 1.f / l1;
    int r0 = qbase + wid * 16 + g;
    size_t ro0 = ((size_t)(b * SS) + r0) * (NHD * DD) + h * DD;
    size_t ro1 = ((size_t)(b * SS) + r0 + 8) * (NHD * DD) + h * DD;
#pragma unroll
    for (int nt = 0; nt < 16; nt++) {
        int c = nt * 8 + 2 * tg;
        float o0 = Oacc[nt][0] * inv0, o1 = Oacc[nt][1] * inv0;
        float o2 = Oacc[nt][2] * inv1, o3 = Oacc[nt][3] * inv1;
        unsigned hp, lp;
        split_pack_h(o0, o1, hp, lp);
        *(unsigned*)(g_oh + ro0 + c) = hp;
        *(unsigned*)(g_ol + ro0 + c) = lp;
        split_pack_h(o2, o3, hp, lp);
        *(unsigned*)(g_oh + ro1 + c) = hp;
        *(unsigned*)(g_ol + ro1 + c) = lp;
    }
#undef FKV
}

// ---------------- launch ----------------
extern "C" void kernel_launch(void* const* d_in, const int* in_sizes, int n_in,
                              void* d_out, int out_size) {
    const int*   positions = (const int*)d_in[0];
    const float* hidden    = (const float*)d_in[1];
    const float* w_qkv     = (const float*)d_in[2];
    const float* w_o       = (const float*)d_in[3];
    float*       out       = (float*)d_out;

    float *qkv;
    __half *hidh, *hidl, *wqTh, *woTh, *oh, *ol;
    cudaGetSymbolAddress((void**)&qkv,  g_qkv);
    cudaGetSymbolAddress((void**)&hidh, g_hidh);
    cudaGetSymbolAddress((void**)&hidl, g_hidl);
    cudaGetSymbolAddress((void**)&wqTh, g_wqTh);
    cudaGetSymbolAddress((void**)&woTh, g_woTh);
    cudaGetSymbolAddress((void**)&oh,   g_oh);
    cudaGetSymbolAddress((void**)&ol,   g_ol);

    cudaFuncSetAttribute(gemm_split_kernel,
                         cudaFuncAttributeMaxDynamicSharedMemorySize, GEMM_SMEM);
    cudaFuncSetAttribute(flash5_kernel,
                         cudaFuncAttributeMaxDynamicSharedMemorySize, FLASH_SMEM);

    // 1) RoPE tables + operand conversions
    build_tables_kernel<<<(SS * HALF + 255) / 256, 256>>>(positions);
    cvt_split_kernel<<<(unsigned)(((size_t)MM * HH + 255) / 256), 256>>>(
        hidden, hidh, hidl, (size_t)MM * HH);
    {
        dim3 grid(CQKV / 32, HH / 32); dim3 blk(32, 8);
        transpose_cvt_kernel<<<grid, blk>>>(w_qkv, HH, CQKV, wqTh);
    }
    {
        dim3 grid(HH / 32, HH / 32); dim3 blk(32, 8);
        transpose_cvt_kernel<<<grid, blk>>>(w_o, HH, HH, woTh);
    }

    // 2) QKV GEMM (2-pass split-A fp16)
    {
        dim3 grid(CQKV / 128, MM / 128);
        gemm_split_kernel<<<grid, 256, GEMM_SMEM>>>(MM, CQKV, HH,
                                                    hidh, hidl, wqTh, qkv);
    }

    // 3) RoPE + scatter (q,k) and V transpose
    rope_scatter_kernel<<<MM, 256>>>();
    {
        dim3 grid(SS / 32, DD / 32, BB * NKVH); dim3 blk(32, 8);
        v_transpose_kernel<<<grid, blk>>>();
    }

    // 4) Flash attention (fp16 single-pass)
    {
        dim3 grid(SS / 128, NHD, BB);
        flash5_kernel<<<grid, 256, FLASH_SMEM>>>();
    }

    // 5) Output projection (2-pass split-A fp16)
    {
        dim3 grid(HH / 128, MM / 128);
        gemm_split_kernel<<<grid, 256, GEMM_SMEM>>>(MM, HH, HH,
                                                    oh, ol, woTh, out);
    }
}

// round 14
// speedup vs baseline: 9.6236x; 1.1984x over previous
#include <cuda_runtime.h>
#include <cuda_bf16.h>
#include <cuda_fp16.h>
#include <math.h>
#include <stdint.h>

#define BB   2
#define SS   2048
#define HH   4096
#define NHD  32
#define NKVH 8
#define DD   128
#define CQKV 6144
#define MM   (BB*SS)         // 4096
#define HALF 64
#define SCALE 0.08838834764831843f

// ---------------- device scratch (allocation-free) ----------------
__device__ float  g_qkv [(size_t)MM*CQKV];
__device__ __half g_hidh[(size_t)MM*HH];                            // A (QKV gemm), single fp16
__device__ __half g_wqTh[(size_t)CQKV*HH];                          // B (QKV gemm), single fp16
__device__ __half g_woTh[(size_t)HH*HH];                            // B (O-proj), single fp16
__device__ __half g_qf[(size_t)BB*NHD*SS*DD];    // fp16 Q (scaled)
__device__ __half g_kf[(size_t)BB*NKVH*SS*DD];   // fp16 K
__device__ __half g_vf[(size_t)BB*NKVH*DD*SS];   // fp16 V^T [b,kh,d,s]
__device__ __half g_oh[(size_t)MM*HH],     g_ol[(size_t)MM*HH];     // A hi/lo (O-proj)
__device__ float  g_cos[SS*HALF], g_sin[SS*HALF];

// ---------------- helpers ----------------
__device__ __forceinline__ void cpa16(unsigned d, const void* s) {
    asm volatile("cp.async.ca.shared.global [%0], [%1], 16;" :: "r"(d), "l"(s));
}
__device__ __forceinline__ void cpa_commit() {
    asm volatile("cp.async.commit_group;");
}
template<int N>
__device__ __forceinline__ void cpa_wait() {
    asm volatile("cp.async.wait_group %0;" :: "n"(N));
}
__device__ __forceinline__ void mma16f(float* c, const unsigned* a, const unsigned* b) {
    asm volatile(
        "mma.sync.aligned.m16n8k16.row.col.f32.f16.f16.f32 "
        "{%0,%1,%2,%3}, {%4,%5,%6,%7}, {%8,%9}, {%0,%1,%2,%3};"
        : "+f"(c[0]), "+f"(c[1]), "+f"(c[2]), "+f"(c[3])
        : "r"(a[0]), "r"(a[1]), "r"(a[2]), "r"(a[3]), "r"(b[0]), "r"(b[1]));
}
__device__ __forceinline__ void ldm4(unsigned* r, unsigned addr) {
    asm volatile("ldmatrix.sync.aligned.m8n8.x4.shared.b16 {%0,%1,%2,%3}, [%4];"
        : "=r"(r[0]), "=r"(r[1]), "=r"(r[2]), "=r"(r[3]) : "r"(addr));
}
__device__ __forceinline__ unsigned pack_h2(float x, float y) {
    __half hx = __float2half_rn(x), hy = __float2half_rn(y);
    return ((unsigned)__half_as_ushort(hy) << 16) | (unsigned)__half_as_ushort(hx);
}
// fp16 hi/lo split-pack of two floats
__device__ __forceinline__ void split_pack_h(float x, float y, unsigned& hp, unsigned& lp) {
    __half xh = __float2half_rn(x), yh = __float2half_rn(y);
    hp = ((unsigned)__half_as_ushort(yh) << 16) | (unsigned)__half_as_ushort(xh);
    __half xl = __float2half_rn(x - __half2float(xh));
    __half yl = __float2half_rn(y - __half2float(yh));
    lp = ((unsigned)__half_as_ushort(yl) << 16) | (unsigned)__half_as_ushort(xl);
}

// ---------------- RoPE tables ----------------
__global__ void build_tables_kernel(const int* __restrict__ positions) {
    int idx = blockIdx.x * blockDim.x + threadIdx.x;
    if (idx >= SS * HALF) return;
    int s = idx >> 6, i = idx & 63;
    double inv = pow(10000.0, -((double)(2 * i)) / (double)DD);
    double ang = (double)positions[s] * inv;
    g_cos[idx] = (float)cos(ang);
    g_sin[idx] = (float)sin(ang);
}

// ---------------- elementwise fp32 -> fp16 ----------------
__global__ void cvt_kernel(const float* __restrict__ src, __half* __restrict__ dh, size_t n) {
    size_t i = (size_t)blockIdx.x * blockDim.x + threadIdx.x;
    if (i >= n) return;
    dh[i] = __float2half_rn(src[i]);
}

// ---------------- transpose + cvt: src [R][C] f32 -> dst [C][R] fp16 ----------------
__global__ void transpose_cvt_kernel(const float* __restrict__ src, int R, int C,
                                     __half* __restrict__ dh) {
    __shared__ float t[32][33];
    int c0 = blockIdx.x * 32, r0 = blockIdx.y * 32;
    for (int i = threadIdx.y; i < 32; i += 8)
        t[i][threadIdx.x] = src[(size_t)(r0 + i) * C + c0 + threadIdx.x];
    __syncthreads();
    for (int i = threadIdx.y; i < 32; i += 8)
        dh[(size_t)(c0 + i) * R + r0 + threadIdx.x] = __float2half_rn(t[threadIdx.x][i]);
}

// ---------------- V transpose -> fp16 [b,kh,d,s] ----------------
__global__ void v_transpose_kernel() {
    __shared__ float t[32][33];
    int s0 = blockIdx.x * 32, d0 = blockIdx.y * 32;
    int bk = blockIdx.z;
    int b = bk / NKVH, kh = bk % NKVH;
    const float* src = g_qkv + (size_t)(b * SS) * CQKV + (NHD * DD + NKVH * DD) + kh * DD;
    for (int i = threadIdx.y; i < 32; i += 8)
        t[i][threadIdx.x] = src[(size_t)(s0 + i) * CQKV + d0 + threadIdx.x];
    __syncthreads();
    __half* dv = g_vf + (size_t)bk * DD * SS;
    for (int i = threadIdx.y; i < 32; i += 8)
        dv[(size_t)(d0 + i) * SS + s0 + threadIdx.x] = __float2half_rn(t[threadIdx.x][i]);
}

// ---------------- RoPE + scatter (q,k) -> fp16 ----------------
__global__ void rope_scatter_kernel() {
    const int m = blockIdx.x;
    const int b = m / SS, s = m % SS;
    const float* row = g_qkv + (size_t)m * CQKV;
    const float* ct = g_cos + s * HALF;
    const float* st = g_sin + s * HALF;

    for (int idx = threadIdx.x; idx < NHD * HALF; idx += blockDim.x) {
        int h = idx >> 6, i = idx & 63;
        float x1 = row[h * DD + i], x2 = row[h * DD + i + HALF];
        float c = ct[i], sn = st[i];
        size_t base = ((size_t)(b * NHD + h) * SS + s) * DD;
        g_qf[base + i]        = __float2half_rn((x1 * c - x2 * sn) * SCALE);
        g_qf[base + i + HALF] = __float2half_rn((x2 * c + x1 * sn) * SCALE);
    }
    for (int idx = threadIdx.x; idx < NKVH * HALF; idx += blockDim.x) {
        int h = idx >> 6, i = idx & 63;
        float x1 = row[NHD * DD + h * DD + i], x2 = row[NHD * DD + h * DD + i + HALF];
        float c = ct[i], sn = st[i];
        size_t base = ((size_t)(b * NKVH + h) * SS + s) * DD;
        g_kf[base + i]        = __float2half_rn(x1 * c - x2 * sn);
        g_kf[base + i + HALF] = __float2half_rn(x2 * c + x1 * sn);
    }
}

// ---------------- fp16 GEMM (HMMA + ldmatrix + L2 swizzle) ----
// C[M][N] = sum_k A[m][k] * Bh[n][k]; if SPLIT, A = Ah + Al (2 passes).
// 128x128x32 tiles, 2-stage cp.async, 256 thr (8 warps 2x4, warp tile 64x32).
#define PW 20            // smem words per row (32 halfs = 16 words + 4 pad)
#define TW (128*PW)
#define GEMM_SMEM_SPLIT  (6*TW*4)
#define GEMM_SMEM_SINGLE (4*TW*4)

template<bool SPLIT>
__global__ __launch_bounds__(256, 1)
void gemm_fp16_kernel(int M, int N, int K,
                      const __half* __restrict__ Ah, const __half* __restrict__ Al,
                      const __half* __restrict__ Bh,
                      float* __restrict__ C) {
    extern __shared__ unsigned sw[];
    const unsigned smemBase = (unsigned)__cvta_generic_to_shared(sw);

    const int tid = threadIdx.x;
    const int wid = tid >> 5, lane = tid & 31;
    const int g = lane >> 2, tg = lane & 3;
    const int wm = wid >> 2, wn = wid & 3;

    // L2-friendly block swizzle: 16-row panels traversed column-by-column
    const int nT = N / 128;
    const int flat = blockIdx.y * gridDim.x + blockIdx.x;
    const int PH = 16;
    const int per = PH * nT;
    const int strip = flat / per;
    const int rem = flat - strip * per;
    const int colT = rem / PH;
    const int rowT = strip * PH + (rem - colT * PH);
    const size_t brow = (size_t)rowT * 128;
    const size_t bcol = (size_t)colT * 128;

    const int lr = tid >> 1, lh = tid & 1;
    const __half* sAh = Ah + (brow + lr) * (size_t)K + lh * 16;
    const __half* sAl = SPLIT ? (Al + (brow + lr) * (size_t)K + lh * 16) : sAh;
    const __half* sBh = Bh + (bcol + lr) * (size_t)K + lh * 16;
    const unsigned soff = (lr * PW + lh * 8) * 4;

    // stage base offsets (words): Ahi st*TW; Alo (2+st)*TW (SPLIT only);
    // B at (SPLIT?4:2 + st)*TW
    const int BOFF = SPLIT ? 4 : 2;

    const unsigned aoff = ((wm * 64 + (lane & 15)) * PW + ((lane & 16) ? 4 : 0)) * 4;
    const unsigned boff = ((wn * 32 + ((lane & 16) >> 1) + (lane & 7)) * PW
                           + ((lane & 8) ? 4 : 0)) * 4;

#define GISSUE(st, k0) {                                                     \
        unsigned a0 = smemBase + ((st) * TW) * 4 + soff;                     \
        cpa16(a0, sAh + (k0)); cpa16(a0 + 16, sAh + (k0) + 8);               \
        if (SPLIT) {                                                         \
            unsigned a1 = smemBase + ((2 + (st)) * TW) * 4 + soff;           \
            cpa16(a1, sAl + (k0)); cpa16(a1 + 16, sAl + (k0) + 8);           \
        }                                                                    \
        unsigned a2 = smemBase + ((BOFF + (st)) * TW) * 4 + soff;            \
        cpa16(a2, sBh + (k0)); cpa16(a2 + 16, sBh + (k0) + 8);               \
    }

    float acc[4][4][4];
#pragma unroll
    for (int mt = 0; mt < 4; mt++)
#pragma unroll
        for (int nt = 0; nt < 4; nt++)
#pragma unroll
            for (int i = 0; i < 4; i++) acc[mt][nt][i] = 0.f;

    const int nIter = K / 32;
    GISSUE(0, 0); cpa_commit();

    for (int it = 0; it < nIter; it++) {
        if (it + 1 < nIter) { GISSUE((it + 1) & 1, (it + 1) * 32); cpa_commit(); cpa_wait<1>(); }
        else                { cpa_wait<0>(); }
        __syncthreads();

        const int st = it & 1;
        const unsigned aHB = smemBase + (st * TW) * 4;
        const unsigned aLB = smemBase + ((2 + st) * TW) * 4;
        const unsigned bHB = smemBase + ((BOFF + st) * TW) * 4;

#pragma unroll
        for (int ks = 0; ks < 2; ks++) {
            const unsigned kb = ks * 32;
            unsigned ah[4][4], al[4][4], bh[2][4];
#pragma unroll
            for (int p = 0; p < 2; p++)
                ldm4(bh[p], bHB + boff + p * 16 * PW * 4 + kb);
#pragma unroll
            for (int mt = 0; mt < 4; mt++) {
                ldm4(ah[mt], aHB + aoff + mt * 16 * PW * 4 + kb);
                if (SPLIT) ldm4(al[mt], aLB + aoff + mt * 16 * PW * 4 + kb);
            }
#pragma unroll
            for (int mt = 0; mt < 4; mt++)
#pragma unroll
                for (int nt = 0; nt < 4; nt++)
                    mma16f(acc[mt][nt], ah[mt], &bh[nt >> 1][(nt & 1) * 2]);
            if (SPLIT) {
#pragma unroll
                for (int mt = 0; mt < 4; mt++)
#pragma unroll
                    for (int nt = 0; nt < 4; nt++)
                        mma16f(acc[mt][nt], al[mt], &bh[nt >> 1][(nt & 1) * 2]);
            }
        }
        __syncthreads();
    }

#pragma unroll
    for (int mt = 0; mt < 4; mt++)
#pragma unroll
        for (int nt = 0; nt < 4; nt++) {
            size_t row = brow + wm * 64 + mt * 16 + g;
            size_t col = bcol + wn * 32 + nt * 8 + 2 * tg;
            *(float2*)(C + row * N + col) = make_float2(acc[mt][nt][0], acc[mt][nt][1]);
            *(float2*)(C + (row + 8) * N + col) = make_float2(acc[mt][nt][2], acc[mt][nt][3]);
        }
#undef GISSUE
}

// ---------------- Flash attention: single-pass fp16, 256 thr, 128 q rows ----
#define KQP 68   // Q/K row pitch in words (128 halfs + pad)
#define VP  36   // V row pitch in words (64 halfs + pad)
#define F_QH 0
#define F_KH(st) (8704 + (st)*4352)
#define F_VH(st) (17408 + (st)*4608)
#define FLASH_SMEM (26624*4)

__global__ __launch_bounds__(256, 1)
void flash5_kernel() {
    extern __shared__ unsigned sw[];
    const unsigned smemBase = (unsigned)__cvta_generic_to_shared(sw);

    const int bx = blockIdx.x, h = blockIdx.y, b = blockIdx.z;
    const int tid = threadIdx.x, wid = tid >> 5, lane = tid & 31;
    const int g = lane >> 2, tg = lane & 3;
    const int qbase = bx * 128;
    const int kh = h >> 2;

    const int qr = tid >> 1, qh2 = tid & 1;
    const int krow = tid >> 2, kq = tid & 3;
    const int vrow = tid >> 1, vh2 = tid & 1;

    const size_t qg0 = ((size_t)(b * NHD + h) * SS + qbase + qr) * DD + qh2 * 64;
    const size_t krowB = (size_t)(b * NKVH + kh) * SS;
    const size_t vg0 = ((size_t)(b * NKVH + kh) * DD + vrow) * SS + vh2 * 32;

    // stage Q (once)
    {
        const __half* sQ = g_qf + qg0;
        unsigned dq = smemBase + (F_QH + qr * KQP + qh2 * 32) * 4;
#pragma unroll
        for (int j = 0; j < 8; j++) cpa16(dq + j * 16, sQ + j * 8);
    }
#define FKV(t, st) {                                                          \
        const __half* sK = g_kf + (krowB + (t) * 64 + krow) * DD + kq * 32;   \
        unsigned dk = smemBase + (F_KH(st) + krow * KQP + kq * 16) * 4;       \
        _Pragma("unroll")                                                     \
        for (int j = 0; j < 4; j++) cpa16(dk + j * 16, sK + j * 8);           \
        const __half* sV = g_vf + vg0 + (t) * 64;                             \
        unsigned dv = smemBase + (F_VH(st) + vrow * VP + vh2 * 16) * 4;       \
        _Pragma("unroll")                                                     \
        for (int j = 0; j < 4; j++) cpa16(dv + j * 16, sV + j * 8);           \
    }

    FKV(0, 0); cpa_commit();

    float Oacc[16][4];
#pragma unroll
    for (int nt = 0; nt < 16; nt++)
#pragma unroll
        for (int i = 0; i < 4; i++) Oacc[nt][i] = 0.f;
    float m0 = -1e30f, m1 = -1e30f, l0 = 0.f, l1 = 0.f;

    const unsigned aoffQ = ((wid * 16 + (lane & 15)) * KQP + ((lane & 16) ? 4 : 0)) * 4;
    const unsigned boffK = ((((lane & 16) >> 1) + (lane & 7)) * KQP + ((lane & 8) ? 4 : 0)) * 4;
    const unsigned boffV = ((((lane & 16) >> 1) + (lane & 7)) * VP + ((lane & 8) ? 4 : 0)) * 4;
    const unsigned qHB = smemBase + F_QH * 4;

    const int ntile = 2 * bx + 2;
    int st = 0;
    for (int t = 0; t < ntile; t++) {
        if (t + 1 < ntile) { FKV(t + 1, st ^ 1); cpa_commit(); cpa_wait<1>(); }
        else               { cpa_wait<0>(); }
        __syncthreads();

        const unsigned kHB = smemBase + F_KH(st) * 4;
        const unsigned vHB = smemBase + F_VH(st) * 4;

        // ---- scores: S(16x64 per warp) = Q @ K^T, single-pass fp16
        float sacc[8][4];
#pragma unroll
        for (int nt = 0; nt < 8; nt++)
#pragma unroll
            for (int i = 0; i < 4; i++) sacc[nt][i] = 0.f;

#pragma unroll
        for (int ks = 0; ks < 8; ks++) {
            const unsigned kb = ks * 32;
            unsigned ah[4], bh[4][4];
            ldm4(ah, qHB + aoffQ + kb);
#pragma unroll
            for (int p = 0; p < 4; p++)
                ldm4(bh[p], kHB + boffK + p * 16 * KQP * 4 + kb);
#pragma unroll
            for (int nt = 0; nt < 8; nt++)
                mma16f(sacc[nt], ah, &bh[nt >> 1][(nt & 1) * 2]);
        }

        // ---- causal mask (tiles overlapping the diagonal)
        if (t >= 2 * bx) {
            int r0 = qbase + wid * 16 + g, r1 = r0 + 8;
#pragma unroll
            for (int nt = 0; nt < 8; nt++) {
                int c0 = t * 64 + nt * 8 + 2 * tg, c1 = c0 + 1;
                if (c0 > r0) sacc[nt][0] = -1e30f;
                if (c1 > r0) sacc[nt][1] = -1e30f;
                if (c0 > r1) sacc[nt][2] = -1e30f;
                if (c1 > r1) sacc[nt][3] = -1e30f;
            }
        }

        // ---- online softmax
        float tm0 = -1e30f, tm1 = -1e30f;
#pragma unroll
        for (int nt = 0; nt < 8; nt++) {
            tm0 = fmaxf(tm0, fmaxf(sacc[nt][0], sacc[nt][1]));
            tm1 = fmaxf(tm1, fmaxf(sacc[nt][2], sacc[nt][3]));
        }
        tm0 = fmaxf(tm0, __shfl_xor_sync(0xffffffffu, tm0, 1));
        tm0 = fmaxf(tm0, __shfl_xor_sync(0xffffffffu, tm0, 2));
        tm1 = fmaxf(tm1, __shfl_xor_sync(0xffffffffu, tm1, 1));
        tm1 = fmaxf(tm1, __shfl_xor_sync(0xffffffffu, tm1, 2));

        float mn0 = fmaxf(m0, tm0), mn1 = fmaxf(m1, tm1);
        float a0 = __expf(m0 - mn0), a1 = __expf(m1 - mn1);
        l0 *= a0; l1 *= a1;
#pragma unroll
        for (int nt = 0; nt < 16; nt++) {
            Oacc[nt][0] *= a0; Oacc[nt][1] *= a0;
            Oacc[nt][2] *= a1; Oacc[nt][3] *= a1;
        }

        float p0a[8], p1a[8], p2a[8], p3a[8];
        float rs0 = 0.f, rs1 = 0.f;
#pragma unroll
        for (int nt = 0; nt < 8; nt++) {
            p0a[nt] = __expf(sacc[nt][0] - mn0);
            p1a[nt] = __expf(sacc[nt][1] - mn0);
            p2a[nt] = __expf(sacc[nt][2] - mn1);
            p3a[nt] = __expf(sacc[nt][3] - mn1);
            rs0 += p0a[nt] + p1a[nt];
            rs1 += p2a[nt] + p3a[nt];
        }
        rs0 += __shfl_xor_sync(0xffffffffu, rs0, 1);
        rs0 += __shfl_xor_sync(0xffffffffu, rs0, 2);
        rs1 += __shfl_xor_sync(0xffffffffu, rs1, 1);
        rs1 += __shfl_xor_sync(0xffffffffu, rs1, 2);
        l0 += rs0; l1 += rs1;
        m0 = mn0; m1 = mn1;

        // ---- PV: O(16x128 per warp) += P(16x64) @ V, single-pass fp16
#pragma unroll
        for (int ks = 0; ks < 4; ks++) {
            const unsigned kb = ks * 32;
            unsigned aH[4];
            aH[0] = pack_h2(p0a[2 * ks],     p1a[2 * ks]);
            aH[1] = pack_h2(p2a[2 * ks],     p3a[2 * ks]);
            aH[2] = pack_h2(p0a[2 * ks + 1], p1a[2 * ks + 1]);
            aH[3] = pack_h2(p2a[2 * ks + 1], p3a[2 * ks + 1]);
#pragma unroll
            for (int p = 0; p < 8; p++) {
                unsigned vbh[4];
                ldm4(vbh, vHB + boffV + p * 16 * VP * 4 + kb);
                mma16f(Oacc[2 * p],     aH, &vbh[0]);
                mma16f(Oacc[2 * p + 1], aH, &vbh[2]);
            }
        }
        __syncthreads();
        st ^= 1;
    }

    // ---- epilogue: O fp16 hi/lo (feeds 2-pass O-proj GEMM)
    float inv0 = 1.f / l0, inv1 = 1.f / l1;
    int r0 = qbase + wid * 16 + g;
    size_t ro0 = ((size_t)(b * SS) + r0) * (NHD * DD) + h * DD;
    size_t ro1 = ((size_t)(b * SS) + r0 + 8) * (NHD * DD) + h * DD;
#pragma unroll
    for (int nt = 0; nt < 16; nt++) {
        int c = nt * 8 + 2 * tg;
        float o0 = Oacc[nt][0] * inv0, o1 = Oacc[nt][1] * inv0;
        float o2 = Oacc[nt][2] * inv1, o3 = Oacc[nt][3] * inv1;
        unsigned hp, lp;
        split_pack_h(o0, o1, hp, lp);
        *(unsigned*)(g_oh + ro0 + c) = hp;
        *(unsigned*)(g_ol + ro0 + c) = lp;
        split_pack_h(o2, o3, hp, lp);
        *(unsigned*)(g_oh + ro1 + c) = hp;
        *(unsigned*)(g_ol + ro1 + c) = lp;
    }
#undef FKV
}

// ---------------- launch ----------------
extern "C" void kernel_launch(void* const* d_in, const int* in_sizes, int n_in,
                              void* d_out, int out_size) {
    const int*   positions = (const int*)d_in[0];
    const float* hidden    = (const float*)d_in[1];
    const float* w_qkv     = (const float*)d_in[2];
    const float* w_o       = (const float*)d_in[3];
    float*       out       = (float*)d_out;

    float *qkv;
    __half *hidh, *wqTh, *woTh, *oh, *ol;
    cudaGetSymbolAddress((void**)&qkv,  g_qkv);
    cudaGetSymbolAddress((void**)&hidh, g_hidh);
    cudaGetSymbolAddress((void**)&wqTh, g_wqTh);
    cudaGetSymbolAddress((void**)&woTh, g_woTh);
    cudaGetSymbolAddress((void**)&oh,   g_oh);
    cudaGetSymbolAddress((void**)&ol,   g_ol);

    cudaFuncSetAttribute(gemm_fp16_kernel<false>,
                         cudaFuncAttributeMaxDynamicSharedMemorySize, GEMM_SMEM_SINGLE);
    cudaFuncSetAttribute(gemm_fp16_kernel<true>,
                         cudaFuncAttributeMaxDynamicSharedMemorySize, GEMM_SMEM_SPLIT);
    cudaFuncSetAttribute(flash5_kernel,
                         cudaFuncAttributeMaxDynamicSharedMemorySize, FLASH_SMEM);

    // 1) RoPE tables + operand conversions
    build_tables_kernel<<<(SS * HALF + 255) / 256, 256>>>(positions);
    cvt_kernel<<<(unsigned)(((size_t)MM * HH + 255) / 256), 256>>>(
        hidden, hidh, (size_t)MM * HH);
    {
        dim3 grid(CQKV / 32, HH / 32); dim3 blk(32, 8);
        transpose_cvt_kernel<<<grid, blk>>>(w_qkv, HH, CQKV, wqTh);
    }
    {
        dim3 grid(HH / 32, HH / 32); dim3 blk(32, 8);
        transpose_cvt_kernel<<<grid, blk>>>(w_o, HH, HH, woTh);
    }

    // 2) QKV GEMM (single-pass fp16)
    {
        dim3 grid(CQKV / 128, MM / 128);
        gemm_fp16_kernel<false><<<grid, 256, GEMM_SMEM_SINGLE>>>(MM, CQKV, HH,
                                                                 hidh, hidh, wqTh, qkv);
    }

    // 3) RoPE + scatter (q,k) and V transpose
    rope_scatter_kernel<<<MM, 256>>>();
    {
        dim3 grid(SS / 32, DD / 32, BB * NKVH); dim3 blk(32, 8);
        v_transpose_kernel<<<grid, blk>>>();
    }

    // 4) Flash attention (fp16 single-pass)
    {
        dim3 grid(SS / 128, NHD, BB);
        flash5_kernel<<<grid, 256, FLASH_SMEM>>>();
    }

    // 5) Output projection (2-pass split-A fp16)
    {
        dim3 grid(HH / 128, MM / 128);
        gemm_fp16_kernel<true><<<grid, 256, GEMM_SMEM_SPLIT>>>(MM, HH, HH,
                                                               oh, ol, woTh, out);
    }
}

// round 17
// speedup vs baseline: 10.8274x; 1.1251x over previous
#include <cuda_runtime.h>
#include <cuda_bf16.h>
#include <cuda_fp16.h>
#include <math.h>
#include <stdint.h>

#define BB   2
#define SS   2048
#define HH   4096
#define NHD  32
#define NKVH 8
#define DD   128
#define CQKV 6144
#define MM   (BB*SS)         // 4096
#define HALF 64
#define SCALE 0.08838834764831843f

// ---------------- device scratch (allocation-free) ----------------
__device__ float  g_qkv [(size_t)MM*CQKV];
__device__ __half g_hidh[(size_t)MM*HH];                            // A (QKV gemm), single fp16
__device__ __half g_wqTh[(size_t)CQKV*HH];                          // B (QKV gemm), single fp16
__device__ __half g_woTh[(size_t)HH*HH];                            // B (O-proj), single fp16
__device__ __half g_qf[(size_t)BB*NHD*SS*DD];    // fp16 Q (scaled)
__device__ __half g_kf[(size_t)BB*NKVH*SS*DD];   // fp16 K
__device__ __half g_vf[(size_t)BB*NKVH*DD*SS];   // fp16 V^T [b,kh,d,s]
__device__ __half g_oh[(size_t)MM*HH],     g_ol[(size_t)MM*HH];     // A hi/lo (O-proj)
__device__ float  g_cos[SS*HALF], g_sin[SS*HALF];

// ---------------- helpers ----------------
__device__ __forceinline__ void cpa16(unsigned d, const void* s) {
    asm volatile("cp.async.ca.shared.global [%0], [%1], 16;" :: "r"(d), "l"(s));
}
__device__ __forceinline__ void cpa_commit() {
    asm volatile("cp.async.commit_group;");
}
template<int N>
__device__ __forceinline__ void cpa_wait() {
    asm volatile("cp.async.wait_group %0;" :: "n"(N));
}
__device__ __forceinline__ void mma16f(float* c, const unsigned* a, const unsigned* b) {
    asm volatile(
        "mma.sync.aligned.m16n8k16.row.col.f32.f16.f16.f32 "
        "{%0,%1,%2,%3}, {%4,%5,%6,%7}, {%8,%9}, {%0,%1,%2,%3};"
        : "+f"(c[0]), "+f"(c[1]), "+f"(c[2]), "+f"(c[3])
        : "r"(a[0]), "r"(a[1]), "r"(a[2]), "r"(a[3]), "r"(b[0]), "r"(b[1]));
}
__device__ __forceinline__ void ldm4(unsigned* r, unsigned addr) {
    asm volatile("ldmatrix.sync.aligned.m8n8.x4.shared.b16 {%0,%1,%2,%3}, [%4];"
        : "=r"(r[0]), "=r"(r[1]), "=r"(r[2]), "=r"(r[3]) : "r"(addr));
}
__device__ __forceinline__ unsigned pack_h2(float x, float y) {
    __half hx = __float2half_rn(x), hy = __float2half_rn(y);
    return ((unsigned)__half_as_ushort(hy) << 16) | (unsigned)__half_as_ushort(hx);
}
// fp16 hi/lo split-pack of two floats
__device__ __forceinline__ void split_pack_h(float x, float y, unsigned& hp, unsigned& lp) {
    __half xh = __float2half_rn(x), yh = __float2half_rn(y);
    hp = ((unsigned)__half_as_ushort(yh) << 16) | (unsigned)__half_as_ushort(xh);
    __half xl = __float2half_rn(x - __half2float(xh));
    __half yl = __float2half_rn(y - __half2float(yh));
    lp = ((unsigned)__half_as_ushort(yl) << 16) | (unsigned)__half_as_ushort(xl);
}

// ---------------- RoPE tables ----------------
__global__ void build_tables_kernel(const int* __restrict__ positions) {
    int idx = blockIdx.x * blockDim.x + threadIdx.x;
    if (idx >= SS * HALF) return;
    int s = idx >> 6, i = idx & 63;
    double inv = pow(10000.0, -((double)(2 * i)) / (double)DD);
    double ang = (double)positions[s] * inv;
    g_cos[idx] = (float)cos(ang);
    g_sin[idx] = (float)sin(ang);
}

// ---------------- elementwise fp32 -> fp16 ----------------
__global__ void cvt_kernel(const float* __restrict__ src, __half* __restrict__ dh, size_t n) {
    size_t i = (size_t)blockIdx.x * blockDim.x + threadIdx.x;
    if (i >= n) return;
    dh[i] = __float2half_rn(src[i]);
}

// ---------------- transpose + cvt: src [R][C] f32 -> dst [C][R] fp16 ----------------
__global__ void transpose_cvt_kernel(const float* __restrict__ src, int R, int C,
                                     __half* __restrict__ dh) {
    __shared__ float t[32][33];
    int c0 = blockIdx.x * 32, r0 = blockIdx.y * 32;
    for (int i = threadIdx.y; i < 32; i += 8)
        t[i][threadIdx.x] = src[(size_t)(r0 + i) * C + c0 + threadIdx.x];
    __syncthreads();
    for (int i = threadIdx.y; i < 32; i += 8)
        dh[(size_t)(c0 + i) * R + r0 + threadIdx.x] = __float2half_rn(t[threadIdx.x][i]);
}

// ---------------- V transpose -> fp16 [b,kh,d,s] ----------------
__global__ void v_transpose_kernel() {
    __shared__ float t[32][33];
    int s0 = blockIdx.x * 32, d0 = blockIdx.y * 32;
    int bk = blockIdx.z;
    int b = bk / NKVH, kh = bk % NKVH;
    const float* src = g_qkv + (size_t)(b * SS) * CQKV + (NHD * DD + NKVH * DD) + kh * DD;
    for (int i = threadIdx.y; i < 32; i += 8)
        t[i][threadIdx.x] = src[(size_t)(s0 + i) * CQKV + d0 + threadIdx.x];
    __syncthreads();
    __half* dv = g_vf + (size_t)bk * DD * SS;
    for (int i = threadIdx.y; i < 32; i += 8)
        dv[(size_t)(d0 + i) * SS + s0 + threadIdx.x] = __float2half_rn(t[threadIdx.x][i]);
}

// ---------------- RoPE + scatter (q,k) -> fp16 ----------------
__global__ void rope_scatter_kernel() {
    const int m = blockIdx.x;
    const int b = m / SS, s = m % SS;
    const float* row = g_qkv + (size_t)m * CQKV;
    const float* ct = g_cos + s * HALF;
    const float* st = g_sin + s * HALF;

    for (int idx = threadIdx.x; idx < NHD * HALF; idx += blockDim.x) {
        int h = idx >> 6, i = idx & 63;
        float x1 = row[h * DD + i], x2 = row[h * DD + i + HALF];
        float c = ct[i], sn = st[i];
        size_t base = ((size_t)(b * NHD + h) * SS + s) * DD;
        g_qf[base + i]        = __float2half_rn((x1 * c - x2 * sn) * SCALE);
        g_qf[base + i + HALF] = __float2half_rn((x2 * c + x1 * sn) * SCALE);
    }
    for (int idx = threadIdx.x; idx < NKVH * HALF; idx += blockDim.x) {
        int h = idx >> 6, i = idx & 63;
        float x1 = row[NHD * DD + h * DD + i], x2 = row[NHD * DD + h * DD + i + HALF];
        float c = ct[i], sn = st[i];
        size_t base = ((size_t)(b * NKVH + h) * SS + s) * DD;
        g_kf[base + i]        = __float2half_rn(x1 * c - x2 * sn);
        g_kf[base + i + HALF] = __float2half_rn(x2 * c + x1 * sn);
    }
}

// ---------------- fp16 GEMM: 256x128 CTA tile, 64x64 warp tile ----------------
// C[M][N] = sum_k A[m][k] * Bh[n][k]; if SPLIT, A = Ah + Al (2 passes).
// 8 warps (4 rows x 2 cols), K chunk 32, 2-stage cp.async.
#define PW 20              // smem words per row (32 halfs = 16 words + 4 pad)
#define TWA (256*PW)       // 5120 words per A stage
#define TWB (128*PW)       // 2560 words per B stage
#define GEMM_SMEM_SPLIT  ((4*TWA + 2*TWB)*4)   // 102400
#define GEMM_SMEM_SINGLE ((2*TWA + 2*TWB)*4)   // 61440

template<bool SPLIT>
__global__ __launch_bounds__(256, 1)
void gemm_fp16_kernel(int M, int N, int K,
                      const __half* __restrict__ Ah, const __half* __restrict__ Al,
                      const __half* __restrict__ Bh,
                      float* __restrict__ C) {
    extern __shared__ unsigned sw[];
    const unsigned smemBase = (unsigned)__cvta_generic_to_shared(sw);

    const int tid = threadIdx.x;
    const int wid = tid >> 5, lane = tid & 31;
    const int g = lane >> 2, tg = lane & 3;
    const int wm = wid >> 1, wn = wid & 1;   // 4 x 2 warp grid

    // column-major tile traversal (row tiles of one column strip stay in L2)
    const int rowTiles = M / 256;            // 16
    const int flat = blockIdx.y * gridDim.x + blockIdx.x;
    const int colT = flat / rowTiles;
    const int rowT = flat - colT * rowTiles;
    const size_t brow = (size_t)rowT * 256;
    const size_t bcol = (size_t)colT * 128;

    const int lr = tid >> 1, lh = tid & 1;   // lr 0..127, lh 0..1
    const __half* sAh0 = Ah + (brow + lr) * (size_t)K + lh * 16;
    const __half* sAh1 = sAh0 + 128 * (size_t)K;
    const __half* sAl0 = SPLIT ? (Al + (brow + lr) * (size_t)K + lh * 16) : sAh0;
    const __half* sAl1 = sAl0 + 128 * (size_t)K;
    const __half* sBh  = Bh + (bcol + lr) * (size_t)K + lh * 16;
    const unsigned soff  = (lr * PW + lh * 8) * 4;
    const unsigned soff1 = soff + 128 * PW * 4;

    const int BBASE = SPLIT ? 4 * TWA : 2 * TWA;   // word offset of B stages

    const unsigned aoff = ((wm * 64 + (lane & 15)) * PW + ((lane & 16) ? 4 : 0)) * 4;
    const unsigned boff = ((wn * 64 + ((lane & 16) >> 1) + (lane & 7)) * PW
                           + ((lane & 8) ? 4 : 0)) * 4;

#define GISSUE(st, k0) {                                                     \
        unsigned a0 = smemBase + ((st) * TWA) * 4 + soff;                    \
        cpa16(a0, sAh0 + (k0)); cpa16(a0 + 16, sAh0 + (k0) + 8);             \
        unsigned a1 = smemBase + ((st) * TWA) * 4 + soff1;                   \
        cpa16(a1, sAh1 + (k0)); cpa16(a1 + 16, sAh1 + (k0) + 8);             \
        if (SPLIT) {                                                         \
            unsigned c0 = smemBase + ((2 + (st)) * TWA) * 4 + soff;          \
            cpa16(c0, sAl0 + (k0)); cpa16(c0 + 16, sAl0 + (k0) + 8);         \
            unsigned c1 = smemBase + ((2 + (st)) * TWA) * 4 + soff1;         \
            cpa16(c1, sAl1 + (k0)); cpa16(c1 + 16, sAl1 + (k0) + 8);         \
        }                                                                    \
        unsigned b0 = smemBase + (BBASE + (st) * TWB) * 4 + soff;            \
        cpa16(b0, sBh + (k0)); cpa16(b0 + 16, sBh + (k0) + 8);               \
    }

    float acc[4][8][4];
#pragma unroll
    for (int mt = 0; mt < 4; mt++)
#pragma unroll
        for (int nt = 0; nt < 8; nt++)
#pragma unroll
            for (int i = 0; i < 4; i++) acc[mt][nt][i] = 0.f;

    const int nIter = K / 32;
    GISSUE(0, 0); cpa_commit();

    for (int it = 0; it < nIter; it++) {
        if (it + 1 < nIter) { GISSUE((it + 1) & 1, (it + 1) * 32); cpa_commit(); cpa_wait<1>(); }
        else                { cpa_wait<0>(); }
        __syncthreads();

        const int st = it & 1;
        const unsigned aHB = smemBase + (st * TWA) * 4;
        const unsigned aLB = smemBase + ((2 + st) * TWA) * 4;
        const unsigned bHB = smemBase + (BBASE + st * TWB) * 4;

#pragma unroll
        for (int ks = 0; ks < 2; ks++) {
            const unsigned kb = ks * 32;
            unsigned ah[4][4], al[4][4], bh[4][4];
#pragma unroll
            for (int p = 0; p < 4; p++)
                ldm4(bh[p], bHB + boff + p * 16 * PW * 4 + kb);
#pragma unroll
            for (int mt = 0; mt < 4; mt++) {
                ldm4(ah[mt], aHB + aoff + mt * 16 * PW * 4 + kb);
                if (SPLIT) ldm4(al[mt], aLB + aoff + mt * 16 * PW * 4 + kb);
            }
#pragma unroll
            for (int mt = 0; mt < 4; mt++)
#pragma unroll
                for (int nt = 0; nt < 8; nt++)
                    mma16f(acc[mt][nt], ah[mt], &bh[nt >> 1][(nt & 1) * 2]);
            if (SPLIT) {
#pragma unroll
                for (int mt = 0; mt < 4; mt++)
#pragma unroll
                    for (int nt = 0; nt < 8; nt++)
                        mma16f(acc[mt][nt], al[mt], &bh[nt >> 1][(nt & 1) * 2]);
            }
        }
        __syncthreads();
    }

#pragma unroll
    for (int mt = 0; mt < 4; mt++)
#pragma unroll
        for (int nt = 0; nt < 8; nt++) {
            size_t row = brow + wm * 64 + mt * 16 + g;
            size_t col = bcol + wn * 64 + nt * 8 + 2 * tg;
            *(float2*)(C + row * N + col) = make_float2(acc[mt][nt][0], acc[mt][nt][1]);
            *(float2*)(C + (row + 8) * N + col) = make_float2(acc[mt][nt][2], acc[mt][nt][3]);
        }
#undef GISSUE
}

// ---------------- Flash attention: single-pass fp16, 256 thr, 128 q rows ----
#define KQP 68   // Q/K row pitch in words (128 halfs + pad)
#define VP  36   // V row pitch in words (64 halfs + pad)
#define F_QH 0
#define F_KH(st) (8704 + (st)*4352)
#define F_VH(st) (17408 + (st)*4608)
#define FLASH_SMEM (26624*4)

__global__ __launch_bounds__(256, 1)
void flash5_kernel() {
    extern __shared__ unsigned sw[];
    const unsigned smemBase = (unsigned)__cvta_generic_to_shared(sw);

    const int bx = blockIdx.x, h = blockIdx.y, b = blockIdx.z;
    const int tid = threadIdx.x, wid = tid >> 5, lane = tid & 31;
    const int g = lane >> 2, tg = lane & 3;
    const int qbase = bx * 128;
    const int kh = h >> 2;

    const int qr = tid >> 1, qh2 = tid & 1;
    const int krow = tid >> 2, kq = tid & 3;
    const int vrow = tid >> 1, vh2 = tid & 1;

    const size_t qg0 = ((size_t)(b * NHD + h) * SS + qbase + qr) * DD + qh2 * 64;
    const size_t krowB = (size_t)(b * NKVH + kh) * SS;
    const size_t vg0 = ((size_t)(b * NKVH + kh) * DD + vrow) * SS + vh2 * 32;

    // stage Q (once)
    {
        const __half* sQ = g_qf + qg0;
        unsigned dq = smemBase + (F_QH + qr * KQP + qh2 * 32) * 4;
#pragma unroll
        for (int j = 0; j < 8; j++) cpa16(dq + j * 16, sQ + j * 8);
    }
#define FKV(t, st) {                                                          \
        const __half* sK = g_kf + (krowB + (t) * 64 + krow) * DD + kq * 32;   \
        unsigned dk = smemBase + (F_KH(st) + krow * KQP + kq * 16) * 4;       \
        _Pragma("unroll")                                                     \
        for (int j = 0; j < 4; j++) cpa16(dk + j * 16, sK + j * 8);           \
        const __half* sV = g_vf + vg0 + (t) * 64;                             \
        unsigned dv = smemBase + (F_VH(st) + vrow * VP + vh2 * 16) * 4;       \
        _Pragma("unroll")                                                     \
        for (int j = 0; j < 4; j++) cpa16(dv + j * 16, sV + j * 8);           \
    }

    FKV(0, 0); cpa_commit();

    float Oacc[16][4];
#pragma unroll
    for (int nt = 0; nt < 16; nt++)
#pragma unroll
        for (int i = 0; i < 4; i++) Oacc[nt][i] = 0.f;
    float m0 = -1e30f, m1 = -1e30f, l0 = 0.f, l1 = 0.f;

    const unsigned aoffQ = ((wid * 16 + (lane & 15)) * KQP + ((lane & 16) ? 4 : 0)) * 4;
    const unsigned boffK = ((((lane & 16) >> 1) + (lane & 7)) * KQP + ((lane & 8) ? 4 : 0)) * 4;
    const unsigned boffV = ((((lane & 16) >> 1) + (lane & 7)) * VP + ((lane & 8) ? 4 : 0)) * 4;
    const unsigned qHB = smemBase + F_QH * 4;

    const int ntile = 2 * bx + 2;
    int st = 0;
    for (int t = 0; t < ntile; t++) {
        if (t + 1 < ntile) { FKV(t + 1, st ^ 1); cpa_commit(); cpa_wait<1>(); }
        else               { cpa_wait<0>(); }
        __syncthreads();

        const unsigned kHB = smemBase + F_KH(st) * 4;
        const unsigned vHB = smemBase + F_VH(st) * 4;

        // ---- scores: S(16x64 per warp) = Q @ K^T, single-pass fp16
        float sacc[8][4];
#pragma unroll
        for (int nt = 0; nt < 8; nt++)
#pragma unroll
            for (int i = 0; i < 4; i++) sacc[nt][i] = 0.f;

#pragma unroll
        for (int ks = 0; ks < 8; ks++) {
            const unsigned kb = ks * 32;
            unsigned ah[4], bh[4][4];
            ldm4(ah, qHB + aoffQ + kb);
#pragma unroll
            for (int p = 0; p < 4; p++)
                ldm4(bh[p], kHB + boffK + p * 16 * KQP * 4 + kb);
#pragma unroll
            for (int nt = 0; nt < 8; nt++)
                mma16f(sacc[nt], ah, &bh[nt >> 1][(nt & 1) * 2]);
        }

        // ---- causal mask (tiles overlapping the diagonal)
        if (t >= 2 * bx) {
            int r0 = qbase + wid * 16 + g, r1 = r0 + 8;
#pragma unroll
            for (int nt = 0; nt < 8; nt++) {
                int c0 = t * 64 + nt * 8 + 2 * tg, c1 = c0 + 1;
                if (c0 > r0) sacc[nt][0] = -1e30f;
                if (c1 > r0) sacc[nt][1] = -1e30f;
                if (c0 > r1) sacc[nt][2] = -1e30f;
                if (c1 > r1) sacc[nt][3] = -1e30f;
            }
        }

        // ---- online softmax
        float tm0 = -1e30f, tm1 = -1e30f;
#pragma unroll
        for (int nt = 0; nt < 8; nt++) {
            tm0 = fmaxf(tm0, fmaxf(sacc[nt][0], sacc[nt][1]));
            tm1 = fmaxf(tm1, fmaxf(sacc[nt][2], sacc[nt][3]));
        }
        tm0 = fmaxf(tm0, __shfl_xor_sync(0xffffffffu, tm0, 1));
        tm0 = fmaxf(tm0, __shfl_xor_sync(0xffffffffu, tm0, 2));
        tm1 = fmaxf(tm1, __shfl_xor_sync(0xffffffffu, tm1, 1));
        tm1 = fmaxf(tm1, __shfl_xor_sync(0xffffffffu, tm1, 2));

        float mn0 = fmaxf(m0, tm0), mn1 = fmaxf(m1, tm1);
        float a0 = __expf(m0 - mn0), a1 = __expf(m1 - mn1);
        l0 *= a0; l1 *= a1;
#pragma unroll
        for (int nt = 0; nt < 16; nt++) {
            Oacc[nt][0] *= a0; Oacc[nt][1] *= a0;
            Oacc[nt][2] *= a1; Oacc[nt][3] *= a1;
        }

        float p0a[8], p1a[8], p2a[8], p3a[8];
        float rs0 = 0.f, rs1 = 0.f;
#pragma unroll
        for (int nt = 0; nt < 8; nt++) {
            p0a[nt] = __expf(sacc[nt][0] - mn0);
            p1a[nt] = __expf(sacc[nt][1] - mn0);
            p2a[nt] = __expf(sacc[nt][2] - mn1);
            p3a[nt] = __expf(sacc[nt][3] - mn1);
            rs0 += p0a[nt] + p1a[nt];
            rs1 += p2a[nt] + p3a[nt];
        }
        rs0 += __shfl_xor_sync(0xffffffffu, rs0, 1);
        rs0 += __shfl_xor_sync(0xffffffffu, rs0, 2);
        rs1 += __shfl_xor_sync(0xffffffffu, rs1, 1);
        rs1 += __shfl_xor_sync(0xffffffffu, rs1, 2);
        l0 += rs0; l1 += rs1;
        m0 = mn0; m1 = mn1;

        // ---- PV: O(16x128 per warp) += P(16x64) @ V, single-pass fp16
#pragma unroll
        for (int ks = 0; ks < 4; ks++) {
            const unsigned kb = ks * 32;
            unsigned aH[4];
            aH[0] = pack_h2(p0a[2 * ks],     p1a[2 * ks]);
            aH[1] = pack_h2(p2a[2 * ks],     p3a[2 * ks]);
            aH[2] = pack_h2(p0a[2 * ks + 1], p1a[2 * ks + 1]);
            aH[3] = pack_h2(p2a[2 * ks + 1], p3a[2 * ks + 1]);
#pragma unroll
            for (int p = 0; p < 8; p++) {
                unsigned vbh[4];
                ldm4(vbh, vHB + boffV + p * 16 * VP * 4 + kb);
                mma16f(Oacc[2 * p],     aH, &vbh[0]);
                mma16f(Oacc[2 * p + 1], aH, &vbh[2]);
            }
        }
        __syncthreads();
        st ^= 1;
    }

    // ---- epilogue: O fp16 hi/lo (feeds 2-pass O-proj GEMM)
    float inv0 = 1.f / l0, inv1 = 1.f / l1;
    int r0 = qbase + wid * 16 + g;
    size_t ro0 = ((size_t)(b * SS) + r0) * (NHD * DD) + h * DD;
    size_t ro1 = ((size_t)(b * SS) + r0 + 8) * (NHD * DD) + h * DD;
#pragma unroll
    for (int nt = 0; nt < 16; nt++) {
        int c = nt * 8 + 2 * tg;
        float o0 = Oacc[nt][0] * inv0, o1 = Oacc[nt][1] * inv0;
        float o2 = Oacc[nt][2] * inv1, o3 = Oacc[nt][3] * inv1;
        unsigned hp, lp;
        split_pack_h(o0, o1, hp, lp);
        *(unsigned*)(g_oh + ro0 + c) = hp;
        *(unsigned*)(g_ol + ro0 + c) = lp;
        split_pack_h(o2, o3, hp, lp);
        *(unsigned*)(g_oh + ro1 + c) = hp;
        *(unsigned*)(g_ol + ro1 + c) = lp;
    }
#undef FKV
}

// ---------------- launch ----------------
extern "C" void kernel_launch(void* const* d_in, const int* in_sizes, int n_in,
                              void* d_out, int out_size) {
    const int*   positions = (const int*)d_in[0];
    const float* hidden    = (const float*)d_in[1];
    const float* w_qkv     = (const float*)d_in[2];
    const float* w_o       = (const float*)d_in[3];
    float*       out       = (float*)d_out;

    float *qkv;
    __half *hidh, *wqTh, *woTh, *oh, *ol;
    cudaGetSymbolAddress((void**)&qkv,  g_qkv);
    cudaGetSymbolAddress((void**)&hidh, g_hidh);
    cudaGetSymbolAddress((void**)&wqTh, g_wqTh);
    cudaGetSymbolAddress((void**)&woTh, g_woTh);
    cudaGetSymbolAddress((void**)&oh,   g_oh);
    cudaGetSymbolAddress((void**)&ol,   g_ol);

    cudaFuncSetAttribute(gemm_fp16_kernel<false>,
                         cudaFuncAttributeMaxDynamicSharedMemorySize, GEMM_SMEM_SINGLE);
    cudaFuncSetAttribute(gemm_fp16_kernel<true>,
                         cudaFuncAttributeMaxDynamicSharedMemorySize, GEMM_SMEM_SPLIT);
    cudaFuncSetAttribute(flash5_kernel,
                         cudaFuncAttributeMaxDynamicSharedMemorySize, FLASH_SMEM);

    // 1) RoPE tables + operand conversions
    build_tables_kernel<<<(SS * HALF + 255) / 256, 256>>>(positions);
    cvt_kernel<<<(unsigned)(((size_t)MM * HH + 255) / 256), 256>>>(
        hidden, hidh, (size_t)MM * HH);
    {
        dim3 grid(CQKV / 32, HH / 32); dim3 blk(32, 8);
        transpose_cvt_kernel<<<grid, blk>>>(w_qkv, HH, CQKV, wqTh);
    }
    {
        dim3 grid(HH / 32, HH / 32); dim3 blk(32, 8);
        transpose_cvt_kernel<<<grid, blk>>>(w_o, HH, HH, woTh);
    }

    // 2) QKV GEMM (single-pass fp16, 256x128 tiles)
    {
        dim3 grid(CQKV / 128, MM / 256);
        gemm_fp16_kernel<false><<<grid, 256, GEMM_SMEM_SINGLE>>>(MM, CQKV, HH,
                                                                 hidh, hidh, wqTh, qkv);
    }

    // 3) RoPE + scatter (q,k) and V transpose
    rope_scatter_kernel<<<MM, 256>>>();
    {
        dim3 grid(SS / 32, DD / 32, BB * NKVH); dim3 blk(32, 8);
        v_transpose_kernel<<<grid, blk>>>();
    }

    // 4) Flash attention (fp16 single-pass)
    {
        dim3 grid(SS / 128, NHD, BB);
        flash5_kernel<<<grid, 256, FLASH_SMEM>>>();
    }

    // 5) Output projection (2-pass split-A fp16, 256x128 tiles)
    {
        dim3 grid(HH / 128, MM / 256);
        gemm_fp16_kernel<true><<<grid, 256, GEMM_SMEM_SPLIT>>>(MM, HH, HH,
                                                               oh, ol, woTh, out);
    }
}